// round 14
// baseline (speedup 1.0000x reference)
#include <cuda_runtime.h>
#include <cuda_bf16.h>
#include <mma.h>
#include <math.h>

using namespace nvcuda;

#define N0 4096
#define EDG 131072

// ---------------- device scratch ----------------
__device__ __nv_bfloat16 dA1b[2048 * 2048];
__device__ __nv_bfloat16 dA1tb[2048 * 2048];
__device__ float dC1[2048 * 2048];
__device__ float dA2[1024 * 1024];
__device__ float dA3[512 * 512];
__device__ float dA4[256 * 256];
__device__ float dBrf[512 * 1024];
__device__ float dBcf[1024 * 512];
__device__ float dP[8 * 4096 * 128];
__device__ float dxs0[4096 * 32];
__device__ float dxs1[2048 * 64];
__device__ float dxs2[1024 * 128];
__device__ float dxs3[512 * 256];
__device__ float dxb[4096 * 512];
__device__ float dybuf[4096 * 512];
__device__ float dzbuf[4096 * 512];
__device__ float ddegall[3840];
__device__ float dinv0[4096], dself0[4096];
__device__ float dinv1[2048], dself1[2048];
__device__ float dinv2[1024], dself2[1024];
__device__ float dinv3[512], dself3[512];
__device__ float dinv4[256], dself4[256];
__device__ float dscorev[4096];
__device__ float dvalsv[2048];
__device__ int dperm0[2048];
__device__ int dperm1[1024];
__device__ int dperm2[512];
__device__ int dperm3[256];
__device__ int dinvi0[4096];
__device__ int dinvi1[2048];
__device__ int dinvi2[1024];
__device__ int dinvi3[512];
__device__ int dcall[4096], dselfn[4096], dcsrc[4096], dcdst[4096];
__device__ int doffS[4097], doffD[4097], dheadS[4096], dheadD[4096];
__device__ int doutl[EDG], dinl[EDG];

// ---------------- helpers ----------------
__device__ __forceinline__ void cpa16(void* s, const void* g) {
    unsigned sa = (unsigned)__cvta_generic_to_shared(s);
    asm volatile("cp.async.cg.shared.global [%0], [%1], 16;\n" ::"r"(sa), "l"(g));
}
__device__ __forceinline__ void cpcommit() { asm volatile("cp.async.commit_group;\n"); }
__device__ __forceinline__ void cpwait1() { asm volatile("cp.async.wait_group 1;\n"); }

__global__ void k_zero(int* __restrict__ call, int* __restrict__ selfn,
                       int* __restrict__ csrc, int* __restrict__ cdst,
                       float* __restrict__ degall) {
    int i = blockIdx.x * 256 + threadIdx.x;
    if (i < 4096) {
        call[i] = 0;
        selfn[i] = 0;
        csrc[i] = 0;
        cdst[i] = 0;
    }
    if (i < 3840) degall[i] = 0.f;
}

// ---------------- sparse build kernels ----------------

__global__ void k_ecnt(const int* __restrict__ ei, int* __restrict__ call,
                       int* __restrict__ selfn, int* __restrict__ csrc,
                       int* __restrict__ cdst) {
    int e = blockIdx.x * 256 + threadIdx.x;
    if (e >= EDG) return;
    int s = ei[e], d = ei[EDG + e];
    atomicAdd(&call[d], 1);
    if (s == d) {
        atomicAdd(&selfn[d], 1);
    } else {
        atomicAdd(&csrc[s], 1);
        atomicAdd(&cdst[d], 1);
    }
}

__global__ void k_scan(const int* __restrict__ c0, int* __restrict__ off0, int* __restrict__ head0,
                       const int* __restrict__ c1, int* __restrict__ off1, int* __restrict__ head1) {
    const int* c = blockIdx.x ? c1 : c0;
    int* off = blockIdx.x ? off1 : off0;
    int* head = blockIdx.x ? head1 : head0;
    __shared__ int sh[1024];
    int tid = threadIdx.x;
    int base = tid * 4;
    int v0 = c[base], v1 = c[base + 1], v2 = c[base + 2], v3 = c[base + 3];
    sh[tid] = v0 + v1 + v2 + v3;
    __syncthreads();
    for (int o = 1; o < 1024; o <<= 1) {
        int x = (tid >= o) ? sh[tid - o] : 0;
        __syncthreads();
        sh[tid] += x;
        __syncthreads();
    }
    int excl = tid ? sh[tid - 1] : 0;
    int p0 = excl, p1 = excl + v0, p2 = p1 + v1, p3 = p2 + v2;
    off[base] = p0; off[base + 1] = p1; off[base + 2] = p2; off[base + 3] = p3;
    head[base] = p0; head[base + 1] = p1; head[base + 2] = p2; head[base + 3] = p3;
    if (tid == 1023) off[4096] = sh[1023];
}

__global__ void k_fill(const int* __restrict__ ei, int* __restrict__ headS,
                       int* __restrict__ headD, int* __restrict__ outl,
                       int* __restrict__ inl) {
    int e = blockIdx.x * 256 + threadIdx.x;
    if (e >= EDG) return;
    int s = ei[e], d = ei[EDG + e];
    if (s == d) return;
    int p = atomicAdd(&headS[s], 1);
    outl[p] = d;
    int q = atomicAdd(&headD[d], 1);
    inl[q] = s;
}

__global__ void k_degfin0(const int* __restrict__ call, const int* __restrict__ selfn,
                          int n, float* __restrict__ dinv, float* __restrict__ selfc) {
    int i = blockIdx.x * 256 + threadIdx.x;
    if (i >= n) return;
    float fill = (selfn[i] == 0) ? 2.0f : 0.0f;
    float d = (float)call[i] + fill;
    float di = (d > 0.f) ? (1.0f / sqrtf(d)) : 0.f;
    dinv[i] = di;
    selfc[i] = di * di * fill;
}

#define MAXD 192
__global__ void k_pairs(const int* __restrict__ offS, const int* __restrict__ outl,
                        const int* __restrict__ offD, const int* __restrict__ inl,
                        const int* __restrict__ inv, float* __restrict__ C1, int ld) {
    int k = blockIdx.x;
    __shared__ int so[MAXD], si[MAXD];
    __shared__ int cnto, cnti;
    int tid = threadIdx.x;
    if (tid == 0) { cnto = 0; cnti = 0; }
    __syncthreads();
    int b0 = offS[k], b1 = offS[k + 1];
    for (int t = b0 + tid; t < b1; t += 256) {
        int r = inv[outl[t]];
        if (r >= 0) { int p = atomicAdd(&cnto, 1); so[p] = r; }
    }
    int c0 = offD[k], c1 = offD[k + 1];
    for (int t = c0 + tid; t < c1; t += 256) {
        int r = inv[inl[t]];
        if (r >= 0) { int p = atomicAdd(&cnti, 1); si[p] = r; }
    }
    __syncthreads();
    int no = cnto, ni = cnti;
    int tot = no * ni;
    for (int t = tid; t < tot; t += 256) {
        int i = t / ni, j = t % ni;
        atomicAdd(&C1[(size_t)so[i] * ld + si[j]], 1.0f);
    }
}

__global__ void k_addA(const int* __restrict__ ei, const int* __restrict__ inv,
                       float* __restrict__ C1, int ld) {
    int e = blockIdx.x * 256 + threadIdx.x;
    if (e >= EDG) return;
    int s = ei[e], d = ei[EDG + e];
    if (s == d) return;
    int rs = inv[s], rd = inv[d];
    if (rs >= 0 && rd >= 0) atomicAdd(&C1[(size_t)rd * ld + rs], 2.0f);
}

__global__ void k_a1fin(const float* __restrict__ C1, __nv_bfloat16* __restrict__ Ab,
                        __nv_bfloat16* __restrict__ AbT, float* __restrict__ deg, int n) {
    __shared__ __nv_bfloat16 tile[32][33];
    int bx = blockIdx.x * 32, by = blockIdx.y * 32;
    int tx = threadIdx.x, ty = threadIdx.y;
    for (int r = ty; r < 32; r += 8) {
        int gi = by + r, gj = bx + tx;
        float v = (gi == gj) ? 0.f : C1[(size_t)gi * n + gj];
        __nv_bfloat16 b = __float2bfloat16(v);
        Ab[(size_t)gi * n + gj] = b;
        tile[r][tx] = b;
    }
    __syncthreads();
    for (int r = ty; r < 32; r += 8)
        AbT[(size_t)(bx + r) * n + by + tx] = tile[tx][r];
    if (ty == 0) {
        float s = 0.f;
        for (int c = 0; c < 32; c++) s += __bfloat162float(tile[tx][c]);
        atomicAdd(&deg[by + tx], s);
    }
}

__global__ void k_degfin2(const float* __restrict__ deg, int n,
                          float* __restrict__ dinv, float* __restrict__ selfc) {
    int i = blockIdx.x * 256 + threadIdx.x;
    if (i >= n) return;
    float d = deg[i] + 2.0f;
    float di = (d > 0.f) ? (1.0f / sqrtf(d)) : 0.f;
    dinv[i] = di;
    selfc[i] = di * di * 2.0f;
}

__global__ void k_sprop(const int* __restrict__ offD, const int* __restrict__ inl,
                        const int* __restrict__ selfn, const float* __restrict__ Z,
                        const float* __restrict__ Y, const float* __restrict__ dinv,
                        const float* __restrict__ selfc, const float* __restrict__ bias,
                        float* __restrict__ O, int c, int dorelu, int dosm) {
    __shared__ float srow[64];
    __shared__ float smx, ssum;
    int d = blockIdx.x;
    int j = threadIdx.x;
    bool act = (j < c);
    float o = 0.f;
    if (act) {
        int b0 = offD[d], b1 = offD[d + 1];
        float acc = 0.f;
        for (int t = b0; t < b1; t++) acc += Z[(size_t)inl[t] * c + j];
        int sn = selfn[d];
        if (sn) acc += (float)sn * Z[(size_t)d * c + j];
        o = dinv[d] * acc + selfc[d] * Y[(size_t)d * c + j] + bias[j];
        if (dorelu) o = fmaxf(o, 0.f);
    }
    if (!dosm) {
        if (act) O[(size_t)d * c + j] = o;
        return;
    }
    srow[j] = act ? o : -1e30f;
    __syncthreads();
    if (j == 0) {
        float m = -1e30f;
        for (int t = 0; t < c; t++) m = fmaxf(m, srow[t]);
        float s = 0.f;
        for (int t = 0; t < c; t++) s += expf(srow[t] - m);
        smx = m;
        ssum = s;
    }
    __syncthreads();
    if (act) O[(size_t)d * c + j] = expf(o - smx) / ssum;
}

// ---------------- XW variants ----------------

__global__ void k_xw(const float* __restrict__ X, const float* __restrict__ W,
                     const float* __restrict__ dinv,
                     float* __restrict__ Y, float* __restrict__ Z,
                     int n, int cin, int cout) {
    int j = blockIdx.x * 32 + threadIdx.x;
    int i = blockIdx.y * 8 + threadIdx.y;
    if (i >= n || j >= cout) return;
    const float* xr = X + (size_t)i * cin;
    float acc = 0.f;
    for (int k = 0; k < cin; k++) acc = fmaf(xr[k], W[(size_t)k * cout + j], acc);
    Y[(size_t)i * cout + j] = acc;
    Z[(size_t)i * cout + j] = acc * dinv[i];
}

__global__ void k_xwp(const float* __restrict__ X, const int* __restrict__ perm,
                      const float* __restrict__ vals, const float* __restrict__ W,
                      const float* __restrict__ dinv,
                      float* __restrict__ Y, float* __restrict__ Z,
                      int n, int cin, int cout) {
    int j = blockIdx.x * 32 + threadIdx.x;
    int i = blockIdx.y * 8 + threadIdx.y;
    if (i >= n || j >= cout) return;
    const float* xr = X + (size_t)perm[i] * cin;
    float acc = 0.f;
    for (int k = 0; k < cin; k++) acc = fmaf(xr[k], W[(size_t)k * cout + j], acc);
    acc *= vals[i];
    Y[(size_t)i * cout + j] = acc;
    Z[(size_t)i * cout + j] = acc * dinv[i];
}

__global__ void k_xwu(const float* __restrict__ R, int c0,
                      const float* __restrict__ Xup, int sup,
                      const int* __restrict__ inv, const float* __restrict__ W,
                      const float* __restrict__ dinv,
                      float* __restrict__ Y, float* __restrict__ Z,
                      int n, int cout) {
    int j = blockIdx.x * 32 + threadIdx.x;
    int i = blockIdx.y * 8 + threadIdx.y;
    if (i >= n || j >= cout) return;
    const float* rr = R + (size_t)i * c0;
    float acc = 0.f;
    for (int k = 0; k < c0; k++) acc = fmaf(rr[k], W[(size_t)k * cout + j], acc);
    int r = inv[i];
    if (r >= 0) {
        const float* xr = Xup + (size_t)r * sup;
        for (int k = 0; k < c0; k++)
            acc = fmaf(xr[k], W[(size_t)(c0 + k) * cout + j], acc);
    }
    Y[(size_t)i * cout + j] = acc;
    Z[(size_t)i * cout + j] = acc * dinv[i];
}

__global__ void k_xwp_cat(const float* __restrict__ X, const int* __restrict__ perm,
                          const float* __restrict__ vals, const float* __restrict__ W,
                          const float* __restrict__ dinv, float* __restrict__ Y,
                          __nv_bfloat16* __restrict__ Zc, int n, int cin, int c) {
    int j = threadIdx.x & 63;
    int i = blockIdx.x * 4 + (threadIdx.x >> 6);
    if (i >= n) return;
    __nv_bfloat16 hb = __float2bfloat16(0.f), lb = hb;
    if (j < c) {
        const float* xr = X + (size_t)perm[i] * cin;
        float acc = 0.f;
        for (int k = 0; k < cin; k++) acc = fmaf(xr[k], W[(size_t)k * c + j], acc);
        acc *= vals[i];
        Y[(size_t)i * c + j] = acc;
        float z = acc * dinv[i];
        hb = __float2bfloat16(z);
        lb = __float2bfloat16(z - __bfloat162float(hb));
    }
    Zc[(size_t)i * 128 + j] = hb;
    Zc[(size_t)i * 128 + 64 + j] = lb;
}

__global__ void k_xwu_cat(const float* __restrict__ R, int c0,
                          const float* __restrict__ Xup, int sup,
                          const int* __restrict__ inv, const float* __restrict__ W,
                          const float* __restrict__ dinv, float* __restrict__ Y,
                          __nv_bfloat16* __restrict__ Zc, int n, int c) {
    int j = threadIdx.x & 63;
    int i = blockIdx.x * 4 + (threadIdx.x >> 6);
    if (i >= n) return;
    __nv_bfloat16 hb = __float2bfloat16(0.f), lb = hb;
    if (j < c) {
        const float* rr = R + (size_t)i * c0;
        float acc = 0.f;
        for (int k = 0; k < c0; k++) acc = fmaf(rr[k], W[(size_t)k * c + j], acc);
        int r = inv[i];
        if (r >= 0) {
            const float* xr = Xup + (size_t)r * sup;
            for (int k = 0; k < c0; k++)
                acc = fmaf(xr[k], W[(size_t)(c0 + k) * c + j], acc);
        }
        Y[(size_t)i * c + j] = acc;
        float z = acc * dinv[i];
        hb = __float2bfloat16(z);
        lb = __float2bfloat16(z - __bfloat162float(hb));
    }
    Zc[(size_t)i * 128 + j] = hb;
    Zc[(size_t)i * 128 + 64 + j] = lb;
}

// ---------------- dense propagation (double-buffered, hi+lo folded) ----------------
#define PROP_SMEM (2 * (64 * 72 + 64 * 136) * 2)
__global__ __launch_bounds__(256) void k_prop(const __nv_bfloat16* __restrict__ A,
                                              const __nv_bfloat16* __restrict__ Zc,
                                              float* __restrict__ P, int n, int KS) {
    extern __shared__ __nv_bfloat16 psm[];
    __nv_bfloat16* Asb = psm;
    __nv_bfloat16* Zsb = psm + 2 * 64 * 72;
    int tid = threadIdx.x;
    int warp = tid >> 5;
    int wm = warp >> 2, wn = warp & 3;
    int m0 = blockIdx.x * 64;
    int ks = blockIdx.y;
    int chunk = n / KS;
    int kbeg = ks * chunk;
    int nIter = chunk >> 6;

    auto load = [&](int b, int k0) {
        __nv_bfloat16* as = Asb + b * 64 * 72;
        __nv_bfloat16* zs = Zsb + b * 64 * 136;
#pragma unroll
        for (int l = 0; l < 2; l++) {
            int e = tid + 256 * l;
            int r = e >> 3, cg = (e & 7) * 8;
            cpa16(as + r * 72 + cg, A + (size_t)(m0 + r) * n + k0 + cg);
        }
#pragma unroll
        for (int l = 0; l < 4; l++) {
            int e = tid + 256 * l;
            int r = e >> 4, cg = (e & 15) * 8;
            cpa16(zs + r * 136 + cg, Zc + (size_t)(k0 + r) * 128 + cg);
        }
        cpcommit();
    };

    wmma::fragment<wmma::accumulator, 16, 16, 16, float> acc[2][2];
#pragma unroll
    for (int i = 0; i < 2; i++)
#pragma unroll
        for (int j = 0; j < 2; j++) wmma::fill_fragment(acc[i][j], 0.f);

    load(0, kbeg);
    for (int it = 0; it < nIter; it++) {
        int cur = it & 1;
        if (it + 1 < nIter) load(cur ^ 1, kbeg + (it + 1) * 64);
        else cpcommit();
        cpwait1();
        __syncthreads();
        __nv_bfloat16* as = Asb + cur * 64 * 72;
        __nv_bfloat16* zs = Zsb + cur * 64 * 136;
#pragma unroll
        for (int kk = 0; kk < 64; kk += 16) {
            wmma::fragment<wmma::matrix_a, 16, 16, 16, __nv_bfloat16, wmma::row_major> af[2];
            wmma::fragment<wmma::matrix_b, 16, 16, 16, __nv_bfloat16, wmma::row_major> bf[2];
#pragma unroll
            for (int i = 0; i < 2; i++)
                wmma::load_matrix_sync(af[i], as + (wm * 32 + 16 * i) * 72 + kk, 72);
#pragma unroll
            for (int j = 0; j < 2; j++)
                wmma::load_matrix_sync(bf[j], zs + kk * 136 + wn * 32 + 16 * j, 136);
#pragma unroll
            for (int i = 0; i < 2; i++)
#pragma unroll
                for (int j = 0; j < 2; j++)
                    wmma::mma_sync(acc[i][j], af[i], bf[j], acc[i][j]);
        }
        __syncthreads();
    }
    float* Cs = reinterpret_cast<float*>(psm);
    const int LDC = 132;
#pragma unroll
    for (int i = 0; i < 2; i++)
#pragma unroll
        for (int j = 0; j < 2; j++)
            wmma::store_matrix_sync(Cs + (wm * 32 + 16 * i) * LDC + wn * 32 + 16 * j,
                                    acc[i][j], LDC, wmma::mem_row_major);
    __syncthreads();
#pragma unroll
    for (int l = 0; l < 16; l++) {
        int e = tid + 256 * l;
        int r = e >> 6, c = e & 63;
        P[((size_t)ks * n + m0 + r) * 64 + c] = Cs[r * LDC + c] + Cs[r * LDC + 64 + c];
    }
}

__global__ void k_prop_epi(const float* __restrict__ P, const float* __restrict__ Y,
                           const float* __restrict__ dinv, const float* __restrict__ selfc,
                           const float* __restrict__ bias, float* __restrict__ O,
                           int n, int c, int KS, int dorelu) {
    int t = blockIdx.x * 256 + threadIdx.x;
    if (t >= n * c) return;
    int i = t / c, j = t % c;
    float s = 0.f;
    for (int ks = 0; ks < KS; ks++) s += P[((size_t)ks * n + i) * 64 + j];
    float o = dinv[i] * s + selfc[i] * Y[t] + bias[j];
    if (dorelu) o = fmaxf(o, 0.f);
    O[t] = o;
}

// fp32 split-K propagation + epilogue
__global__ __launch_bounds__(256) void k_gcnmm_sp(
    const float* __restrict__ A, const float* __restrict__ Z,
    float* __restrict__ P, int n, int c, int KS) {
    __shared__ float As[32][65];
    __shared__ float Zs[32][32];
    int tid = threadIdx.x;
    int m0 = blockIdx.y * 64;
    int n0c = blockIdx.x * 32;
    int ks = blockIdx.z;
    int chunk = n / KS;
    int kbeg = ks * chunk, kend = kbeg + chunk;
    int r0 = tid >> 5, colt = tid & 31;
    float acc[8] = {0, 0, 0, 0, 0, 0, 0, 0};
    for (int k0 = kbeg; k0 < kend; k0 += 32) {
#pragma unroll
        for (int l = 0; l < 2; l++) {
            int e = tid + 256 * l;
            int row = e >> 3, qc = (e & 7) * 4;
            float4 v = *reinterpret_cast<const float4*>(A + (size_t)(m0 + row) * n + k0 + qc);
            As[qc + 0][row] = v.x; As[qc + 1][row] = v.y;
            As[qc + 2][row] = v.z; As[qc + 3][row] = v.w;
        }
        {
            int row = tid >> 3, qc = (tid & 7) * 4;
            int gk = k0 + row;
#pragma unroll
            for (int u = 0; u < 4; u++) {
                int gc = n0c + qc + u;
                Zs[row][qc + u] = (gc < c) ? Z[(size_t)gk * c + gc] : 0.f;
            }
        }
        __syncthreads();
#pragma unroll
        for (int k = 0; k < 32; k++) {
            float zv = Zs[k][colt];
#pragma unroll
            for (int u = 0; u < 8; u++) acc[u] = fmaf(As[k][r0 + 8 * u], zv, acc[u]);
        }
        __syncthreads();
    }
    int gc = n0c + colt;
    if (gc < c) {
#pragma unroll
        for (int u = 0; u < 8; u++) {
            int gi = m0 + r0 + 8 * u;
            P[((size_t)ks * n + gi) * c + gc] = acc[u];
        }
    }
}

__global__ void k_gcn_epi(const float* __restrict__ P, const float* __restrict__ Y,
                          const float* __restrict__ dinv, const float* __restrict__ selfc,
                          const float* __restrict__ bias, float* __restrict__ O,
                          int n, int c, int KS, int dorelu) {
    int t = blockIdx.x * 256 + threadIdx.x;
    if (t >= n * c) return;
    int i = t / c, j = t % c;
    float s = 0.f;
    size_t stride = (size_t)n * c;
    for (int ks = 0; ks < KS; ks++) s += P[ks * stride + t];
    float o = dinv[i] * s + selfc[i] * Y[t] + bias[j];
    if (dorelu) o = fmaxf(o, 0.f);
    O[t] = o;
}

// ---- split-K fused gather + augment GEMM partial (WMMA, 3-stage cp.async) ----
// blockIdx.z = K-slice. Writes partial 128x128 tiles to P[ks].
#define AUG_SMEM (3 * 2 * 128 * 72 * 2)
#define KS_AUG 4
__global__ __launch_bounds__(256) void k_aug(const __nv_bfloat16* __restrict__ A,
                                             const __nv_bfloat16* __restrict__ AT,
                                             const int* __restrict__ permv,
                                             int K, int Nn, float* __restrict__ P) {
    extern __shared__ char smraw[];
    __nv_bfloat16* AsB = reinterpret_cast<__nv_bfloat16*>(smraw);
    __nv_bfloat16* BsB = AsB + 3 * 128 * 72;
    __shared__ int spa[128], spb[128];
    const int LDK = 72;
    int tid = threadIdx.x;
    int warp = tid >> 5;
    int wm = warp >> 2, wn = warp & 3;
    int m0 = blockIdx.y * 128, n0 = blockIdx.x * 128;
    int ks = blockIdx.z;
    int sliceK = K / KS_AUG;
    int kbase = ks * sliceK;

    if (tid < 128) spa[tid] = permv[m0 + tid];
    else spb[tid - 128] = permv[n0 + tid - 128];
    __syncthreads();

    auto load_tiles = [&](int st, int k0) {
        __nv_bfloat16* as = AsB + st * 128 * LDK;
        __nv_bfloat16* bs = BsB + st * 128 * LDK;
#pragma unroll
        for (int l = 0; l < 4; l++) {
            int e = tid + 256 * l;
            int r = e >> 3, cg = (e & 7) * 8;
            cpa16(as + r * LDK + cg, A + (size_t)spa[r] * K + k0 + cg);
            cpa16(bs + r * LDK + cg, AT + (size_t)spb[r] * K + k0 + cg);
        }
        cpcommit();
    };

    wmma::fragment<wmma::accumulator, 16, 16, 16, float> acc[4][2];
#pragma unroll
    for (int i = 0; i < 4; i++)
#pragma unroll
        for (int j = 0; j < 2; j++) wmma::fill_fragment(acc[i][j], 0.f);

    int nIter = sliceK / 64;
    load_tiles(0, kbase);
    load_tiles(1, kbase + 64);
    for (int it = 0; it < nIter; it++) {
        int st = it % 3;
        cpwait1();
        __syncthreads();
        int k0 = kbase + it * 64;
        if (tid < 128) {
            int d = spa[tid] - k0;
            if (d >= 0 && d < 64) AsB[st * 128 * LDK + tid * LDK + d] = __float2bfloat16(1.f);
        } else {
            int r = tid - 128;
            int d = spb[r] - k0;
            if (d >= 0 && d < 64) BsB[st * 128 * LDK + r * LDK + d] = __float2bfloat16(1.f);
        }
        __syncthreads();
        if (it + 2 < nIter) load_tiles((it + 2) % 3, kbase + (it + 2) * 64);
        __nv_bfloat16* as = AsB + st * 128 * LDK;
        __nv_bfloat16* bs = BsB + st * 128 * LDK;
#pragma unroll
        for (int kk = 0; kk < 64; kk += 16) {
            wmma::fragment<wmma::matrix_a, 16, 16, 16, __nv_bfloat16, wmma::row_major> af[4];
            wmma::fragment<wmma::matrix_b, 16, 16, 16, __nv_bfloat16, wmma::col_major> bf[2];
#pragma unroll
            for (int i = 0; i < 4; i++)
                wmma::load_matrix_sync(af[i], as + (wm * 64 + 16 * i) * LDK + kk, LDK);
#pragma unroll
            for (int j = 0; j < 2; j++)
                wmma::load_matrix_sync(bf[j], bs + (wn * 32 + 16 * j) * LDK + kk, LDK);
#pragma unroll
            for (int i = 0; i < 4; i++)
#pragma unroll
                for (int j = 0; j < 2; j++)
                    wmma::mma_sync(acc[i][j], af[i], bf[j], acc[i][j]);
        }
    }
    // store partial tile directly to P[ks]
#pragma unroll
    for (int i = 0; i < 4; i++)
#pragma unroll
        for (int j = 0; j < 2; j++)
            wmma::store_matrix_sync(
                P + ((size_t)ks * Nn + m0 + wm * 64 + 16 * i) * Nn + n0 + wn * 32 + 16 * j,
                acc[i][j], Nn, wmma::mem_row_major);
}

// split-K fp32 SGEMM partial for L3/L4 (gathered operands)
__global__ __launch_bounds__(256) void k_gemm64(const float* __restrict__ Br,
                                                const float* __restrict__ Bc,
                                                float* __restrict__ P, int K, int Nn,
                                                int KS) {
    __shared__ float As[16][65];
    __shared__ float Bs[16][65];
    int tid = threadIdx.x;
    int m0 = blockIdx.y * 64, n0 = blockIdx.x * 64;
    int ks = blockIdx.z;
    int sliceK = K / KS;
    int kbeg = ks * sliceK, kend = kbeg + sliceK;
    int ty = tid >> 4, tx = tid & 15;
    float acc[4][4] = {};
    for (int k0 = kbeg; k0 < kend; k0 += 16) {
#pragma unroll
        for (int l = 0; l < 4; l++) {
            int e = tid + 256 * l;
            int row = e >> 4, kk = e & 15;
            As[kk][row] = Br[(size_t)(m0 + row) * K + k0 + kk];
        }
#pragma unroll
        for (int l = 0; l < 4; l++) {
            int e = tid + 256 * l;
            int row = e >> 6, col = e & 63;
            Bs[row][col] = Bc[(size_t)(k0 + row) * Nn + n0 + col];
        }
        __syncthreads();
#pragma unroll
        for (int kk = 0; kk < 16; kk++) {
            float a[4], b[4];
#pragma unroll
            for (int i = 0; i < 4; i++) a[i] = As[kk][ty * 4 + i];
#pragma unroll
            for (int j = 0; j < 4; j++) b[j] = Bs[kk][tx * 4 + j];
#pragma unroll
            for (int i = 0; i < 4; i++)
#pragma unroll
                for (int j = 0; j < 4; j++) acc[i][j] = fmaf(a[i], b[j], acc[i][j]);
        }
        __syncthreads();
    }
#pragma unroll
    for (int i = 0; i < 4; i++)
#pragma unroll
        for (int j = 0; j < 4; j++)
            P[((size_t)ks * Nn + m0 + ty * 4 + i) * Nn + n0 + tx * 4 + j] = acc[i][j];
}

// generic split-K finalize: C = sum_ks P, diag->0, deg row sums. 4 cols/thread.
__global__ void k_gfin(const float* __restrict__ P, float* __restrict__ C,
                       float* __restrict__ deg, int M, int Nn, int KS) {
    int t = blockIdx.x * 256 + threadIdx.x;
    int tot = M * (Nn / 4);
    if (t >= tot) return;
    int r = t / (Nn / 4);
    int cq = (t % (Nn / 4)) * 4;
    float v[4] = {0, 0, 0, 0};
    for (int ks = 0; ks < KS; ks++) {
        const float* pr = P + ((size_t)ks * M + r) * Nn + cq;
#pragma unroll
        for (int u = 0; u < 4; u++) v[u] += pr[u];
    }
    float rs = 0.f;
#pragma unroll
    for (int u = 0; u < 4; u++) {
        if (r == cq + u) v[u] = 0.f;
        rs += v[u];
    }
    float4 o = {v[0], v[1], v[2], v[3]};
    *reinterpret_cast<float4*>(C + (size_t)r * Nn + cq) = o;
    atomicAdd(&deg[r], rs);
}

__global__ void k_grow_f32(const float* __restrict__ A, int n,
                           const int* __restrict__ perm, int ksel,
                           float* __restrict__ Br) {
    size_t t = (size_t)blockIdx.x * 256 + threadIdx.x;
    if (t >= (size_t)ksel * n) return;
    int r = t / n, k = t % n;
    int pr = perm[r];
    Br[t] = (k == pr) ? 1.0f : A[(size_t)pr * n + k];
}

__global__ void k_gcol_f32(const float* __restrict__ A, int n,
                           const int* __restrict__ perm, int ksel,
                           float* __restrict__ Bc) {
    size_t t = (size_t)blockIdx.x * 256 + threadIdx.x;
    if (t >= (size_t)n * ksel) return;
    int k = t / ksel, c = t % ksel;
    int pc = perm[c];
    Bc[t] = (k == pc) ? 1.0f : A[(size_t)k * n + pc];
}

// ---------------- misc ----------------

__global__ void k_score(const float* __restrict__ X, const float* __restrict__ w,
                        int n, int c, float* __restrict__ score) {
    int row = blockIdx.x;
    __shared__ float sh[128];
    const float* xr = X + (size_t)row * c;
    float wsq = 0.f, dot = 0.f;
    for (int k = threadIdx.x; k < c; k += 128) {
        float wv = w[k];
        wsq += wv * wv;
        dot += xr[k] * wv;
    }
    sh[threadIdx.x] = wsq;
    __syncthreads();
    for (int o = 64; o > 0; o >>= 1) {
        if (threadIdx.x < o) sh[threadIdx.x] += sh[threadIdx.x + o];
        __syncthreads();
    }
    float wn = sh[0];
    __syncthreads();
    sh[threadIdx.x] = dot;
    __syncthreads();
    for (int o = 64; o > 0; o >>= 1) {
        if (threadIdx.x < o) sh[threadIdx.x] += sh[threadIdx.x + o];
        __syncthreads();
    }
    if (threadIdx.x == 0) score[row] = tanhf(sh[0] / sqrtf(wn));
}

__global__ void k_rank(const float* __restrict__ score, int n, int k,
                       int* __restrict__ perm, float* __restrict__ vals,
                       int* __restrict__ inv) {
    __shared__ float ss[1024];
    int i = blockIdx.x * 256 + threadIdx.x;
    float si = (i < n) ? score[i] : 0.f;
    int rank = 0;
    for (int t0 = 0; t0 < n; t0 += 1024) {
#pragma unroll
        for (int l = 0; l < 4; l++) {
            int idx = threadIdx.x + 256 * l;
            int g = t0 + idx;
            ss[idx] = (g < n) ? score[g] : -1e30f;
        }
        __syncthreads();
#pragma unroll 8
        for (int jj = 0; jj < 1024; jj++) {
            float sj = ss[jj];
            int j = t0 + jj;
            rank += (sj > si) || (sj == si && j < i);
        }
        __syncthreads();
    }
    if (i >= n) return;
    if (rank < k) {
        perm[rank] = i;
        vals[rank] = si;
        inv[i] = rank;
    } else {
        inv[i] = -1;
    }
}

// ---------------- host orchestration ----------------

struct Ptrs {
    float *y, *z, *P;
    __nv_bfloat16* zc;
};

static void prop_tc(const __nv_bfloat16* Ab, int n, const float* b, int c, bool relu,
                    float* out, const float* dinv, const float* selfc, const Ptrs& q) {
    const int KS = 8;
    k_prop<<<dim3(n / 64, KS), 256, PROP_SMEM>>>(Ab, q.zc, q.P, n, KS);
    k_prop_epi<<<(n * c + 255) / 256, 256>>>(q.P, q.y, dinv, selfc, b, out, n, c, KS, relu ? 1 : 0);
}

static void prop_f32(const float* A, int n, const float* b, int c, bool relu,
                     float* out, const float* dinv, const float* selfc, const Ptrs& q) {
    const int KS = 8;
    dim3 g2((c + 31) / 32, n / 64, KS);
    k_gcnmm_sp<<<g2, 256>>>(A, q.z, q.P, n, c, KS);
    k_gcn_epi<<<(n * c + 255) / 256, 256>>>(q.P, q.y, dinv, selfc, b, out, n, c, KS, relu ? 1 : 0);
}

extern "C" void kernel_launch(void* const* d_in, const int* in_sizes, int n_in,
                              void* d_out, int out_size) {
    const float* x = (const float*)d_in[0];
    const int* ei = (const int*)d_in[1];
    const float *Wd[5], *bd[5], *p[4], *Wu[4], *bu[4];
    for (int i = 0; i < 5; i++) { Wd[i] = (const float*)d_in[2 + 2 * i]; bd[i] = (const float*)d_in[3 + 2 * i]; }
    for (int i = 0; i < 4; i++) p[i] = (const float*)d_in[12 + i];
    for (int i = 0; i < 4; i++) { Wu[i] = (const float*)d_in[16 + 2 * i]; bu[i] = (const float*)d_in[17 + 2 * i]; }
    const float* Wo = (const float*)d_in[24];
    const float* bo = (const float*)d_in[25];

    static bool attrset = false;
    if (!attrset) {
        cudaFuncSetAttribute(k_aug, cudaFuncAttributeMaxDynamicSharedMemorySize, AUG_SMEM);
        cudaFuncSetAttribute(k_prop, cudaFuncAttributeMaxDynamicSharedMemorySize, PROP_SMEM);
        attrset = true;
    }

    __nv_bfloat16 *A1b, *A1tb;
    float *C1, *A2, *A3, *A4, *xs0, *xs1, *xs2, *xs3, *xb;
    float *Brf, *Bcf, *score, *vals, *degall;
    float *di0, *sf0, *di1, *sf1, *di2, *sf2, *di3, *sf3, *di4, *sf4;
    int *pm0, *pm1, *pm2, *pm3;
    int *iv0, *iv1, *iv2, *iv3;
    int *call, *selfn, *csrc, *cdst, *offS, *offD, *headS, *headD, *outl, *inl;
    Ptrs q;
    cudaGetSymbolAddress((void**)&A1b, dA1b);
    cudaGetSymbolAddress((void**)&A1tb, dA1tb);
    cudaGetSymbolAddress((void**)&C1, dC1);
    cudaGetSymbolAddress((void**)&A2, dA2);
    cudaGetSymbolAddress((void**)&A3, dA3);
    cudaGetSymbolAddress((void**)&A4, dA4);
    cudaGetSymbolAddress((void**)&Brf, dBrf);
    cudaGetSymbolAddress((void**)&Bcf, dBcf);
    cudaGetSymbolAddress((void**)&q.P, dP);
    cudaGetSymbolAddress((void**)&xs0, dxs0);
    cudaGetSymbolAddress((void**)&xs1, dxs1);
    cudaGetSymbolAddress((void**)&xs2, dxs2);
    cudaGetSymbolAddress((void**)&xs3, dxs3);
    cudaGetSymbolAddress((void**)&xb, dxb);
    cudaGetSymbolAddress((void**)&q.y, dybuf);
    cudaGetSymbolAddress((void**)&q.z, dzbuf);
    q.zc = (__nv_bfloat16*)q.z;
    cudaGetSymbolAddress((void**)&degall, ddegall);
    cudaGetSymbolAddress((void**)&di0, dinv0); cudaGetSymbolAddress((void**)&sf0, dself0);
    cudaGetSymbolAddress((void**)&di1, dinv1); cudaGetSymbolAddress((void**)&sf1, dself1);
    cudaGetSymbolAddress((void**)&di2, dinv2); cudaGetSymbolAddress((void**)&sf2, dself2);
    cudaGetSymbolAddress((void**)&di3, dinv3); cudaGetSymbolAddress((void**)&sf3, dself3);
    cudaGetSymbolAddress((void**)&di4, dinv4); cudaGetSymbolAddress((void**)&sf4, dself4);
    cudaGetSymbolAddress((void**)&score, dscorev);
    cudaGetSymbolAddress((void**)&vals, dvalsv);
    cudaGetSymbolAddress((void**)&pm0, dperm0);
    cudaGetSymbolAddress((void**)&pm1, dperm1);
    cudaGetSymbolAddress((void**)&pm2, dperm2);
    cudaGetSymbolAddress((void**)&pm3, dperm3);
    cudaGetSymbolAddress((void**)&iv0, dinvi0);
    cudaGetSymbolAddress((void**)&iv1, dinvi1);
    cudaGetSymbolAddress((void**)&iv2, dinvi2);
    cudaGetSymbolAddress((void**)&iv3, dinvi3);
    cudaGetSymbolAddress((void**)&call, dcall);
    cudaGetSymbolAddress((void**)&selfn, dselfn);
    cudaGetSymbolAddress((void**)&csrc, dcsrc);
    cudaGetSymbolAddress((void**)&cdst, dcdst);
    cudaGetSymbolAddress((void**)&offS, doffS);
    cudaGetSymbolAddress((void**)&offD, doffD);
    cudaGetSymbolAddress((void**)&headS, dheadS);
    cudaGetSymbolAddress((void**)&headD, dheadD);
    cudaGetSymbolAddress((void**)&outl, doutl);
    cudaGetSymbolAddress((void**)&inl, dinl);

    float* degL1 = degall;
    float* degL2 = degall + 2048;
    float* degL3 = degall + 3072;
    float* degL4 = degall + 3584;

    // ---- build sparse adjacency structures ----
    k_zero<<<16, 256>>>(call, selfn, csrc, cdst, degall);
    cudaMemsetAsync(C1, 0, (size_t)2048 * 2048 * sizeof(float));
    k_ecnt<<<EDG / 256, 256>>>(ei, call, selfn, csrc, cdst);
    k_scan<<<2, 1024>>>(csrc, offS, headS, cdst, offD, headD);
    k_fill<<<EDG / 256, 256>>>(ei, headS, headD, outl, inl);
    k_degfin0<<<N0 / 256, 256>>>(call, selfn, N0, di0, sf0);

    // GCN0 (sparse)
    {
        dim3 bx(32, 8);
        k_xw<<<dim3(1, 512), bx>>>(x, Wd[0], di0, q.y, q.z, 4096, 128, 32);
        k_sprop<<<4096, 64>>>(offD, inl, selfn, q.z, q.y, di0, sf0, bd[0], xs0, 32, 1, 0);
    }

    // ---- level 1: sparse path-pair augment ----
    k_score<<<4096, 128>>>(xs0, p[0], 4096, 32, score);
    k_rank<<<16, 256>>>(score, 4096, 2048, pm0, vals, iv0);
    k_pairs<<<4096, 256>>>(offS, outl, offD, inl, iv0, C1, 2048);
    k_addA<<<EDG / 256, 256>>>(ei, iv0, C1, 2048);
    k_a1fin<<<dim3(2048 / 32, 2048 / 32), dim3(32, 8)>>>(C1, A1b, A1tb, degL1, 2048);
    k_degfin2<<<2048 / 256, 256>>>(degL1, 2048, di1, sf1);
    k_xwp_cat<<<2048 / 4, 256>>>(xs0, pm0, vals, Wd[1], di1, q.y, q.zc, 2048, 32, 64);
    prop_tc(A1b, 2048, bd[1], 64, true, xs1, di1, sf1, q);

    // ---- level 2: split-K fused gather+augment ----
    k_score<<<2048, 128>>>(xs1, p[1], 2048, 64, score);
    k_rank<<<8, 256>>>(score, 2048, 1024, pm1, vals, iv1);
    k_aug<<<dim3(8, 8, KS_AUG), 256, AUG_SMEM>>>(A1b, A1tb, pm1, 2048, 1024, q.P);
    k_gfin<<<(1024 * 256 + 255) / 256, 256>>>(q.P, A2, degL2, 1024, 1024, KS_AUG);
    k_degfin2<<<1024 / 256, 256>>>(degL2, 1024, di2, sf2);
    {
        dim3 bx(32, 8);
        k_xwp<<<dim3(4, 128), bx>>>(xs1, pm1, vals, Wd[2], di2, q.y, q.z, 1024, 64, 128);
        prop_f32(A2, 1024, bd[2], 128, true, xs2, di2, sf2, q);
    }

    // ---- level 3: split-K gather + SGEMM ----
    k_score<<<1024, 128>>>(xs2, p[2], 1024, 128, score);
    k_rank<<<4, 256>>>(score, 1024, 512, pm2, vals, iv2);
    k_grow_f32<<<(512 * 1024 + 255) / 256, 256>>>(A2, 1024, pm2, 512, Brf);
    k_gcol_f32<<<(1024 * 512 + 255) / 256, 256>>>(A2, 1024, pm2, 512, Bcf);
    k_gemm64<<<dim3(8, 8, 4), 256>>>(Brf, Bcf, q.P, 1024, 512, 4);
    k_gfin<<<(512 * 128 + 255) / 256, 256>>>(q.P, A3, degL3, 512, 512, 4);
    k_degfin2<<<512 / 256, 256>>>(degL3, 512, di3, sf3);
    {
        dim3 bx(32, 8);
        k_xwp<<<dim3(8, 64), bx>>>(xs2, pm2, vals, Wd[3], di3, q.y, q.z, 512, 128, 256);
        prop_f32(A3, 512, bd[3], 256, true, xs3, di3, sf3, q);
    }

    // ---- level 4: split-K gather + SGEMM ----
    k_score<<<512, 128>>>(xs3, p[3], 512, 256, score);
    k_rank<<<2, 256>>>(score, 512, 256, pm3, vals, iv3);
    k_grow_f32<<<(256 * 512 + 255) / 256, 256>>>(A3, 512, pm3, 256, Brf);
    k_gcol_f32<<<(512 * 256 + 255) / 256, 256>>>(A3, 512, pm3, 256, Bcf);
    k_gemm64<<<dim3(4, 4, 4), 256>>>(Brf, Bcf, q.P, 512, 256, 4);
    k_gfin<<<(256 * 64 + 255) / 256, 256>>>(q.P, A4, degL4, 256, 256, 4);
    k_degfin2<<<1, 256>>>(degL4, 256, di4, sf4);
    {
        dim3 bx(32, 8);
        k_xwp<<<dim3(16, 32), bx>>>(xs3, pm3, vals, Wd[4], di4, q.y, q.z, 256, 256, 512);
        prop_f32(A4, 256, bd[4], 512, true, xb, di4, sf4, q);
    }

    // ---- up 0 ----
    {
        dim3 bx(32, 8);
        k_xwu<<<dim3(8, 64), bx>>>(xs3, 256, xb, 512, iv3, Wu[0], di3, q.y, q.z, 512, 256);
        prop_f32(A3, 512, bu[0], 256, true, xb, di3, sf3, q);
    }
    // ---- up 1 ----
    {
        dim3 bx(32, 8);
        k_xwu<<<dim3(4, 128), bx>>>(xs2, 128, xb, 256, iv2, Wu[1], di2, q.y, q.z, 1024, 128);
        prop_f32(A2, 1024, bu[1], 128, true, xb, di2, sf2, q);
    }
    // ---- up 2 (tc) ----
    k_xwu_cat<<<2048 / 4, 256>>>(xs1, 64, xb, 128, iv1, Wu[2], di1, q.y, q.zc, 2048, 64);
    prop_tc(A1b, 2048, bu[2], 64, true, xb, di1, sf1, q);

    // ---- up 3 (sparse), NO relu ----
    {
        dim3 bx(32, 8);
        k_xwu<<<dim3(1, 512), bx>>>(xs0, 32, xb, 64, iv0, Wu[3], di0, q.y, q.z, 4096, 32);
        k_sprop<<<4096, 64>>>(offD, inl, selfn, q.z, q.y, di0, sf0, bu[3], xb, 32, 0, 0);
    }

    // ---- final GCN (sparse) + fused softmax -> d_out ----
    {
        dim3 bx(32, 8);
        k_xw<<<dim3(2, 512), bx>>>(xb, Wo, di0, q.y, q.z, 4096, 32, 37);
        k_sprop<<<4096, 64>>>(offD, inl, selfn, q.z, q.y, di0, sf0, bo, (float*)d_out, 37, 0, 1);
    }
}

// round 15
// speedup vs baseline: 1.0627x; 1.0627x over previous
#include <cuda_runtime.h>
#include <cuda_bf16.h>
#include <mma.h>
#include <math.h>

using namespace nvcuda;

#define N0 4096
#define EDG 131072

// ---------------- device scratch ----------------
__device__ __nv_bfloat16 dA1b[2048 * 2048];
__device__ __nv_bfloat16 dA1tb[2048 * 2048];
__device__ float dC1[2048 * 2048];
__device__ float dA2[1024 * 1024];
__device__ float dA3[512 * 512];
__device__ float dA4[256 * 256];
__device__ float dBrf[512 * 1024];
__device__ float dBcf[1024 * 512];
__device__ float dP[8 * 4096 * 128];
__device__ float dxs0[4096 * 32];
__device__ float dxs1[2048 * 64];
__device__ float dxs2[1024 * 128];
__device__ float dxs3[512 * 256];
__device__ float dxb[4096 * 512];
__device__ float dybuf[4096 * 512];
__device__ float dzbuf[4096 * 512];
__device__ float ddegall[3840];
__device__ float dinv0[4096], dself0[4096];
__device__ float dinv1[2048], dself1[2048];
__device__ float dinv2[1024], dself2[1024];
__device__ float dinv3[512], dself3[512];
__device__ float dinv4[256], dself4[256];
__device__ float dscorev[4096];
__device__ float dvalsv[2048];
__device__ int dperm0[2048];
__device__ int dperm1[1024];
__device__ int dperm2[512];
__device__ int dperm3[256];
__device__ int dinvi0[4096];
__device__ int dinvi1[2048];
__device__ int dinvi2[1024];
__device__ int dinvi3[512];
__device__ int dcall[4096], dselfn[4096], dcsrc[4096], dcdst[4096];
__device__ int doffS[4097], doffD[4097], dheadS[4096], dheadD[4096];
__device__ int doutl[EDG], dinl[EDG];

// ---------------- helpers ----------------
__device__ __forceinline__ void cpa16(void* s, const void* g) {
    unsigned sa = (unsigned)__cvta_generic_to_shared(s);
    asm volatile("cp.async.cg.shared.global [%0], [%1], 16;\n" ::"r"(sa), "l"(g));
}
__device__ __forceinline__ void cpcommit() { asm volatile("cp.async.commit_group;\n"); }
__device__ __forceinline__ void cpwait1() { asm volatile("cp.async.wait_group 1;\n"); }

__global__ void k_zero(int* __restrict__ call, int* __restrict__ selfn,
                       int* __restrict__ csrc, int* __restrict__ cdst,
                       float* __restrict__ degall) {
    int i = blockIdx.x * 256 + threadIdx.x;
    if (i < 4096) {
        call[i] = 0;
        selfn[i] = 0;
        csrc[i] = 0;
        cdst[i] = 0;
    }
    if (i < 3840) degall[i] = 0.f;
}

// ---------------- sparse build kernels ----------------

__global__ void k_ecnt(const int* __restrict__ ei, int* __restrict__ call,
                       int* __restrict__ selfn, int* __restrict__ csrc,
                       int* __restrict__ cdst) {
    int e = blockIdx.x * 256 + threadIdx.x;
    if (e >= EDG) return;
    int s = ei[e], d = ei[EDG + e];
    atomicAdd(&call[d], 1);
    if (s == d) {
        atomicAdd(&selfn[d], 1);
    } else {
        atomicAdd(&csrc[s], 1);
        atomicAdd(&cdst[d], 1);
    }
}

__global__ void k_scan(const int* __restrict__ c0, int* __restrict__ off0, int* __restrict__ head0,
                       const int* __restrict__ c1, int* __restrict__ off1, int* __restrict__ head1) {
    const int* c = blockIdx.x ? c1 : c0;
    int* off = blockIdx.x ? off1 : off0;
    int* head = blockIdx.x ? head1 : head0;
    __shared__ int sh[1024];
    int tid = threadIdx.x;
    int base = tid * 4;
    int v0 = c[base], v1 = c[base + 1], v2 = c[base + 2], v3 = c[base + 3];
    sh[tid] = v0 + v1 + v2 + v3;
    __syncthreads();
    for (int o = 1; o < 1024; o <<= 1) {
        int x = (tid >= o) ? sh[tid - o] : 0;
        __syncthreads();
        sh[tid] += x;
        __syncthreads();
    }
    int excl = tid ? sh[tid - 1] : 0;
    int p0 = excl, p1 = excl + v0, p2 = p1 + v1, p3 = p2 + v2;
    off[base] = p0; off[base + 1] = p1; off[base + 2] = p2; off[base + 3] = p3;
    head[base] = p0; head[base + 1] = p1; head[base + 2] = p2; head[base + 3] = p3;
    if (tid == 1023) off[4096] = sh[1023];
}

__global__ void k_fill(const int* __restrict__ ei, int* __restrict__ headS,
                       int* __restrict__ headD, int* __restrict__ outl,
                       int* __restrict__ inl) {
    int e = blockIdx.x * 256 + threadIdx.x;
    if (e >= EDG) return;
    int s = ei[e], d = ei[EDG + e];
    if (s == d) return;
    int p = atomicAdd(&headS[s], 1);
    outl[p] = d;
    int q = atomicAdd(&headD[d], 1);
    inl[q] = s;
}

__global__ void k_degfin0(const int* __restrict__ call, const int* __restrict__ selfn,
                          int n, float* __restrict__ dinv, float* __restrict__ selfc) {
    int i = blockIdx.x * 256 + threadIdx.x;
    if (i >= n) return;
    float fill = (selfn[i] == 0) ? 2.0f : 0.0f;
    float d = (float)call[i] + fill;
    float di = (d > 0.f) ? (1.0f / sqrtf(d)) : 0.f;
    dinv[i] = di;
    selfc[i] = di * di * fill;
}

#define MAXD 192
__global__ void k_pairs(const int* __restrict__ offS, const int* __restrict__ outl,
                        const int* __restrict__ offD, const int* __restrict__ inl,
                        const int* __restrict__ inv, float* __restrict__ C1, int ld) {
    int k = blockIdx.x;
    __shared__ int so[MAXD], si[MAXD];
    __shared__ int cnto, cnti;
    int tid = threadIdx.x;
    if (tid == 0) { cnto = 0; cnti = 0; }
    __syncthreads();
    int b0 = offS[k], b1 = offS[k + 1];
    for (int t = b0 + tid; t < b1; t += 256) {
        int r = inv[outl[t]];
        if (r >= 0) { int p = atomicAdd(&cnto, 1); so[p] = r; }
    }
    int c0 = offD[k], c1 = offD[k + 1];
    for (int t = c0 + tid; t < c1; t += 256) {
        int r = inv[inl[t]];
        if (r >= 0) { int p = atomicAdd(&cnti, 1); si[p] = r; }
    }
    __syncthreads();
    int no = cnto, ni = cnti;
    int tot = no * ni;
    for (int t = tid; t < tot; t += 256) {
        int i = t / ni, j = t % ni;
        atomicAdd(&C1[(size_t)so[i] * ld + si[j]], 1.0f);
    }
}

__global__ void k_addA(const int* __restrict__ ei, const int* __restrict__ inv,
                       float* __restrict__ C1, int ld) {
    int e = blockIdx.x * 256 + threadIdx.x;
    if (e >= EDG) return;
    int s = ei[e], d = ei[EDG + e];
    if (s == d) return;
    int rs = inv[s], rd = inv[d];
    if (rs >= 0 && rd >= 0) atomicAdd(&C1[(size_t)rd * ld + rs], 2.0f);
}

__global__ void k_a1fin(const float* __restrict__ C1, __nv_bfloat16* __restrict__ Ab,
                        __nv_bfloat16* __restrict__ AbT, float* __restrict__ deg, int n) {
    __shared__ __nv_bfloat16 tile[32][33];
    int bx = blockIdx.x * 32, by = blockIdx.y * 32;
    int tx = threadIdx.x, ty = threadIdx.y;
    for (int r = ty; r < 32; r += 8) {
        int gi = by + r, gj = bx + tx;
        float v = (gi == gj) ? 0.f : C1[(size_t)gi * n + gj];
        __nv_bfloat16 b = __float2bfloat16(v);
        Ab[(size_t)gi * n + gj] = b;
        tile[r][tx] = b;
    }
    __syncthreads();
    for (int r = ty; r < 32; r += 8)
        AbT[(size_t)(bx + r) * n + by + tx] = tile[tx][r];
    if (ty == 0) {
        float s = 0.f;
        for (int c = 0; c < 32; c++) s += __bfloat162float(tile[tx][c]);
        atomicAdd(&deg[by + tx], s);
    }
}

__global__ void k_degfin2(const float* __restrict__ deg, int n,
                          float* __restrict__ dinv, float* __restrict__ selfc) {
    int i = blockIdx.x * 256 + threadIdx.x;
    if (i >= n) return;
    float d = deg[i] + 2.0f;
    float di = (d > 0.f) ? (1.0f / sqrtf(d)) : 0.f;
    dinv[i] = di;
    selfc[i] = di * di * 2.0f;
}

__global__ void k_sprop(const int* __restrict__ offD, const int* __restrict__ inl,
                        const int* __restrict__ selfn, const float* __restrict__ Z,
                        const float* __restrict__ Y, const float* __restrict__ dinv,
                        const float* __restrict__ selfc, const float* __restrict__ bias,
                        float* __restrict__ O, int c, int dorelu, int dosm) {
    __shared__ float srow[64];
    __shared__ float smx, ssum;
    int d = blockIdx.x;
    int j = threadIdx.x;
    bool act = (j < c);
    float o = 0.f;
    if (act) {
        int b0 = offD[d], b1 = offD[d + 1];
        float acc = 0.f;
        for (int t = b0; t < b1; t++) acc += Z[(size_t)inl[t] * c + j];
        int sn = selfn[d];
        if (sn) acc += (float)sn * Z[(size_t)d * c + j];
        o = dinv[d] * acc + selfc[d] * Y[(size_t)d * c + j] + bias[j];
        if (dorelu) o = fmaxf(o, 0.f);
    }
    if (!dosm) {
        if (act) O[(size_t)d * c + j] = o;
        return;
    }
    srow[j] = act ? o : -1e30f;
    __syncthreads();
    if (j == 0) {
        float m = -1e30f;
        for (int t = 0; t < c; t++) m = fmaxf(m, srow[t]);
        float s = 0.f;
        for (int t = 0; t < c; t++) s += expf(srow[t] - m);
        smx = m;
        ssum = s;
    }
    __syncthreads();
    if (act) O[(size_t)d * c + j] = expf(o - smx) / ssum;
}

// ---------------- XW variants ----------------

__global__ void k_xw(const float* __restrict__ X, const float* __restrict__ W,
                     const float* __restrict__ dinv,
                     float* __restrict__ Y, float* __restrict__ Z,
                     int n, int cin, int cout) {
    int j = blockIdx.x * 32 + threadIdx.x;
    int i = blockIdx.y * 8 + threadIdx.y;
    if (i >= n || j >= cout) return;
    const float* xr = X + (size_t)i * cin;
    float acc = 0.f;
    for (int k = 0; k < cin; k++) acc = fmaf(xr[k], W[(size_t)k * cout + j], acc);
    Y[(size_t)i * cout + j] = acc;
    Z[(size_t)i * cout + j] = acc * dinv[i];
}

__global__ void k_xwp(const float* __restrict__ X, const int* __restrict__ perm,
                      const float* __restrict__ vals, const float* __restrict__ W,
                      const float* __restrict__ dinv,
                      float* __restrict__ Y, float* __restrict__ Z,
                      int n, int cin, int cout) {
    int j = blockIdx.x * 32 + threadIdx.x;
    int i = blockIdx.y * 8 + threadIdx.y;
    if (i >= n || j >= cout) return;
    const float* xr = X + (size_t)perm[i] * cin;
    float acc = 0.f;
    for (int k = 0; k < cin; k++) acc = fmaf(xr[k], W[(size_t)k * cout + j], acc);
    acc *= vals[i];
    Y[(size_t)i * cout + j] = acc;
    Z[(size_t)i * cout + j] = acc * dinv[i];
}

__global__ void k_xwu(const float* __restrict__ R, int c0,
                      const float* __restrict__ Xup, int sup,
                      const int* __restrict__ inv, const float* __restrict__ W,
                      const float* __restrict__ dinv,
                      float* __restrict__ Y, float* __restrict__ Z,
                      int n, int cout) {
    int j = blockIdx.x * 32 + threadIdx.x;
    int i = blockIdx.y * 8 + threadIdx.y;
    if (i >= n || j >= cout) return;
    const float* rr = R + (size_t)i * c0;
    float acc = 0.f;
    for (int k = 0; k < c0; k++) acc = fmaf(rr[k], W[(size_t)k * cout + j], acc);
    int r = inv[i];
    if (r >= 0) {
        const float* xr = Xup + (size_t)r * sup;
        for (int k = 0; k < c0; k++)
            acc = fmaf(xr[k], W[(size_t)(c0 + k) * cout + j], acc);
    }
    Y[(size_t)i * cout + j] = acc;
    Z[(size_t)i * cout + j] = acc * dinv[i];
}

__global__ void k_xwp_cat(const float* __restrict__ X, const int* __restrict__ perm,
                          const float* __restrict__ vals, const float* __restrict__ W,
                          const float* __restrict__ dinv, float* __restrict__ Y,
                          __nv_bfloat16* __restrict__ Zc, int n, int cin, int c) {
    int j = threadIdx.x & 63;
    int i = blockIdx.x * 4 + (threadIdx.x >> 6);
    if (i >= n) return;
    __nv_bfloat16 hb = __float2bfloat16(0.f), lb = hb;
    if (j < c) {
        const float* xr = X + (size_t)perm[i] * cin;
        float acc = 0.f;
        for (int k = 0; k < cin; k++) acc = fmaf(xr[k], W[(size_t)k * c + j], acc);
        acc *= vals[i];
        Y[(size_t)i * c + j] = acc;
        float z = acc * dinv[i];
        hb = __float2bfloat16(z);
        lb = __float2bfloat16(z - __bfloat162float(hb));
    }
    Zc[(size_t)i * 128 + j] = hb;
    Zc[(size_t)i * 128 + 64 + j] = lb;
}

__global__ void k_xwu_cat(const float* __restrict__ R, int c0,
                          const float* __restrict__ Xup, int sup,
                          const int* __restrict__ inv, const float* __restrict__ W,
                          const float* __restrict__ dinv, float* __restrict__ Y,
                          __nv_bfloat16* __restrict__ Zc, int n, int c) {
    int j = threadIdx.x & 63;
    int i = blockIdx.x * 4 + (threadIdx.x >> 6);
    if (i >= n) return;
    __nv_bfloat16 hb = __float2bfloat16(0.f), lb = hb;
    if (j < c) {
        const float* rr = R + (size_t)i * c0;
        float acc = 0.f;
        for (int k = 0; k < c0; k++) acc = fmaf(rr[k], W[(size_t)k * c + j], acc);
        int r = inv[i];
        if (r >= 0) {
            const float* xr = Xup + (size_t)r * sup;
            for (int k = 0; k < c0; k++)
                acc = fmaf(xr[k], W[(size_t)(c0 + k) * c + j], acc);
        }
        Y[(size_t)i * c + j] = acc;
        float z = acc * dinv[i];
        hb = __float2bfloat16(z);
        lb = __float2bfloat16(z - __bfloat162float(hb));
    }
    Zc[(size_t)i * 128 + j] = hb;
    Zc[(size_t)i * 128 + 64 + j] = lb;
}

// ---------------- dense propagation (double-buffered, hi+lo folded) ----------------
#define PROP_SMEM (2 * (64 * 72 + 64 * 136) * 2)
__global__ __launch_bounds__(256) void k_prop(const __nv_bfloat16* __restrict__ A,
                                              const __nv_bfloat16* __restrict__ Zc,
                                              float* __restrict__ P, int n, int KS) {
    extern __shared__ __nv_bfloat16 psm[];
    __nv_bfloat16* Asb = psm;
    __nv_bfloat16* Zsb = psm + 2 * 64 * 72;
    int tid = threadIdx.x;
    int warp = tid >> 5;
    int wm = warp >> 2, wn = warp & 3;
    int m0 = blockIdx.x * 64;
    int ks = blockIdx.y;
    int chunk = n / KS;
    int kbeg = ks * chunk;
    int nIter = chunk >> 6;

    auto load = [&](int b, int k0) {
        __nv_bfloat16* as = Asb + b * 64 * 72;
        __nv_bfloat16* zs = Zsb + b * 64 * 136;
#pragma unroll
        for (int l = 0; l < 2; l++) {
            int e = tid + 256 * l;
            int r = e >> 3, cg = (e & 7) * 8;
            cpa16(as + r * 72 + cg, A + (size_t)(m0 + r) * n + k0 + cg);
        }
#pragma unroll
        for (int l = 0; l < 4; l++) {
            int e = tid + 256 * l;
            int r = e >> 4, cg = (e & 15) * 8;
            cpa16(zs + r * 136 + cg, Zc + (size_t)(k0 + r) * 128 + cg);
        }
        cpcommit();
    };

    wmma::fragment<wmma::accumulator, 16, 16, 16, float> acc[2][2];
#pragma unroll
    for (int i = 0; i < 2; i++)
#pragma unroll
        for (int j = 0; j < 2; j++) wmma::fill_fragment(acc[i][j], 0.f);

    load(0, kbeg);
    for (int it = 0; it < nIter; it++) {
        int cur = it & 1;
        if (it + 1 < nIter) load(cur ^ 1, kbeg + (it + 1) * 64);
        else cpcommit();
        cpwait1();
        __syncthreads();
        __nv_bfloat16* as = Asb + cur * 64 * 72;
        __nv_bfloat16* zs = Zsb + cur * 64 * 136;
#pragma unroll
        for (int kk = 0; kk < 64; kk += 16) {
            wmma::fragment<wmma::matrix_a, 16, 16, 16, __nv_bfloat16, wmma::row_major> af[2];
            wmma::fragment<wmma::matrix_b, 16, 16, 16, __nv_bfloat16, wmma::row_major> bf[2];
#pragma unroll
            for (int i = 0; i < 2; i++)
                wmma::load_matrix_sync(af[i], as + (wm * 32 + 16 * i) * 72 + kk, 72);
#pragma unroll
            for (int j = 0; j < 2; j++)
                wmma::load_matrix_sync(bf[j], zs + kk * 136 + wn * 32 + 16 * j, 136);
#pragma unroll
            for (int i = 0; i < 2; i++)
#pragma unroll
                for (int j = 0; j < 2; j++)
                    wmma::mma_sync(acc[i][j], af[i], bf[j], acc[i][j]);
        }
        __syncthreads();
    }
    float* Cs = reinterpret_cast<float*>(psm);
    const int LDC = 132;
#pragma unroll
    for (int i = 0; i < 2; i++)
#pragma unroll
        for (int j = 0; j < 2; j++)
            wmma::store_matrix_sync(Cs + (wm * 32 + 16 * i) * LDC + wn * 32 + 16 * j,
                                    acc[i][j], LDC, wmma::mem_row_major);
    __syncthreads();
#pragma unroll
    for (int l = 0; l < 16; l++) {
        int e = tid + 256 * l;
        int r = e >> 6, c = e & 63;
        P[((size_t)ks * n + m0 + r) * 64 + c] = Cs[r * LDC + c] + Cs[r * LDC + 64 + c];
    }
}

__global__ void k_prop_epi(const float* __restrict__ P, const float* __restrict__ Y,
                           const float* __restrict__ dinv, const float* __restrict__ selfc,
                           const float* __restrict__ bias, float* __restrict__ O,
                           int n, int c, int KS, int dorelu) {
    int t = blockIdx.x * 256 + threadIdx.x;
    if (t >= n * c) return;
    int i = t / c, j = t % c;
    float s = 0.f;
    for (int ks = 0; ks < KS; ks++) s += P[((size_t)ks * n + i) * 64 + j];
    float o = dinv[i] * s + selfc[i] * Y[t] + bias[j];
    if (dorelu) o = fmaxf(o, 0.f);
    O[t] = o;
}

// fp32 split-K propagation + epilogue
__global__ __launch_bounds__(256) void k_gcnmm_sp(
    const float* __restrict__ A, const float* __restrict__ Z,
    float* __restrict__ P, int n, int c, int KS) {
    __shared__ float As[32][65];
    __shared__ float Zs[32][32];
    int tid = threadIdx.x;
    int m0 = blockIdx.y * 64;
    int n0c = blockIdx.x * 32;
    int ks = blockIdx.z;
    int chunk = n / KS;
    int kbeg = ks * chunk, kend = kbeg + chunk;
    int r0 = tid >> 5, colt = tid & 31;
    float acc[8] = {0, 0, 0, 0, 0, 0, 0, 0};
    for (int k0 = kbeg; k0 < kend; k0 += 32) {
#pragma unroll
        for (int l = 0; l < 2; l++) {
            int e = tid + 256 * l;
            int row = e >> 3, qc = (e & 7) * 4;
            float4 v = *reinterpret_cast<const float4*>(A + (size_t)(m0 + row) * n + k0 + qc);
            As[qc + 0][row] = v.x; As[qc + 1][row] = v.y;
            As[qc + 2][row] = v.z; As[qc + 3][row] = v.w;
        }
        {
            int row = tid >> 3, qc = (tid & 7) * 4;
            int gk = k0 + row;
#pragma unroll
            for (int u = 0; u < 4; u++) {
                int gc = n0c + qc + u;
                Zs[row][qc + u] = (gc < c) ? Z[(size_t)gk * c + gc] : 0.f;
            }
        }
        __syncthreads();
#pragma unroll
        for (int k = 0; k < 32; k++) {
            float zv = Zs[k][colt];
#pragma unroll
            for (int u = 0; u < 8; u++) acc[u] = fmaf(As[k][r0 + 8 * u], zv, acc[u]);
        }
        __syncthreads();
    }
    int gc = n0c + colt;
    if (gc < c) {
#pragma unroll
        for (int u = 0; u < 8; u++) {
            int gi = m0 + r0 + 8 * u;
            P[((size_t)ks * n + gi) * c + gc] = acc[u];
        }
    }
}

__global__ void k_gcn_epi(const float* __restrict__ P, const float* __restrict__ Y,
                          const float* __restrict__ dinv, const float* __restrict__ selfc,
                          const float* __restrict__ bias, float* __restrict__ O,
                          int n, int c, int KS, int dorelu) {
    int t = blockIdx.x * 256 + threadIdx.x;
    if (t >= n * c) return;
    int i = t / c, j = t % c;
    float s = 0.f;
    size_t stride = (size_t)n * c;
    for (int ks = 0; ks < KS; ks++) s += P[ks * stride + t];
    float o = dinv[i] * s + selfc[i] * Y[t] + bias[j];
    if (dorelu) o = fmaxf(o, 0.f);
    O[t] = o;
}

// ---- fused gather + augment GEMM (WMMA, 3-stage cp.async) — L2 ----
#define AUG_SMEM (3 * 2 * 128 * 72 * 2)
__global__ __launch_bounds__(256) void k_aug(const __nv_bfloat16* __restrict__ A,
                                             const __nv_bfloat16* __restrict__ AT,
                                             const int* __restrict__ permv,
                                             int K, int Nn, float* __restrict__ C,
                                             float* __restrict__ deg) {
    extern __shared__ char smraw[];
    __nv_bfloat16* AsB = reinterpret_cast<__nv_bfloat16*>(smraw);
    __nv_bfloat16* BsB = AsB + 3 * 128 * 72;
    __shared__ int spa[128], spb[128];
    const int LDK = 72;
    int tid = threadIdx.x;
    int warp = tid >> 5;
    int wm = warp >> 2, wn = warp & 3;
    int m0 = blockIdx.y * 128, n0 = blockIdx.x * 128;

    if (tid < 128) spa[tid] = permv[m0 + tid];
    else spb[tid - 128] = permv[n0 + tid - 128];
    __syncthreads();

    auto load_tiles = [&](int st, int k0) {
        __nv_bfloat16* as = AsB + st * 128 * LDK;
        __nv_bfloat16* bs = BsB + st * 128 * LDK;
#pragma unroll
        for (int l = 0; l < 4; l++) {
            int e = tid + 256 * l;
            int r = e >> 3, cg = (e & 7) * 8;
            cpa16(as + r * LDK + cg, A + (size_t)spa[r] * K + k0 + cg);
            cpa16(bs + r * LDK + cg, AT + (size_t)spb[r] * K + k0 + cg);
        }
        cpcommit();
    };

    wmma::fragment<wmma::accumulator, 16, 16, 16, float> acc[4][2];
#pragma unroll
    for (int i = 0; i < 4; i++)
#pragma unroll
        for (int j = 0; j < 2; j++) wmma::fill_fragment(acc[i][j], 0.f);

    int nIter = K / 64;
    load_tiles(0, 0);
    load_tiles(1, 64);
    for (int it = 0; it < nIter; it++) {
        int st = it % 3;
        cpwait1();
        __syncthreads();
        int k0 = it * 64;
        if (tid < 128) {
            int d = spa[tid] - k0;
            if (d >= 0 && d < 64) AsB[st * 128 * LDK + tid * LDK + d] = __float2bfloat16(1.f);
        } else {
            int r = tid - 128;
            int d = spb[r] - k0;
            if (d >= 0 && d < 64) BsB[st * 128 * LDK + r * LDK + d] = __float2bfloat16(1.f);
        }
        __syncthreads();
        if (it + 2 < nIter) load_tiles((it + 2) % 3, (it + 2) * 64);
        __nv_bfloat16* as = AsB + st * 128 * LDK;
        __nv_bfloat16* bs = BsB + st * 128 * LDK;
#pragma unroll
        for (int kk = 0; kk < 64; kk += 16) {
            wmma::fragment<wmma::matrix_a, 16, 16, 16, __nv_bfloat16, wmma::row_major> af[4];
            wmma::fragment<wmma::matrix_b, 16, 16, 16, __nv_bfloat16, wmma::col_major> bf[2];
#pragma unroll
            for (int i = 0; i < 4; i++)
                wmma::load_matrix_sync(af[i], as + (wm * 64 + 16 * i) * LDK + kk, LDK);
#pragma unroll
            for (int j = 0; j < 2; j++)
                wmma::load_matrix_sync(bf[j], bs + (wn * 32 + 16 * j) * LDK + kk, LDK);
#pragma unroll
            for (int i = 0; i < 4; i++)
#pragma unroll
                for (int j = 0; j < 2; j++)
                    wmma::mma_sync(acc[i][j], af[i], bf[j], acc[i][j]);
        }
    }
    __syncthreads();
    float* Cs = reinterpret_cast<float*>(smraw);
    const int LDC = 132;
#pragma unroll
    for (int i = 0; i < 4; i++)
#pragma unroll
        for (int j = 0; j < 2; j++)
            wmma::store_matrix_sync(Cs + (wm * 64 + 16 * i) * LDC + wn * 32 + 16 * j,
                                    acc[i][j], LDC, wmma::mem_row_major);
    __syncthreads();
    if (m0 == n0 && tid < 128) Cs[tid * LDC + tid] = 0.f;
    __syncthreads();
#pragma unroll
    for (int l = 0; l < 16; l++) {
        int e = tid + 256 * l;
        int r = e >> 5, cq = (e & 31) * 4;
        float4 v;
        v.x = Cs[r * LDC + cq];
        v.y = Cs[r * LDC + cq + 1];
        v.z = Cs[r * LDC + cq + 2];
        v.w = Cs[r * LDC + cq + 3];
        *reinterpret_cast<float4*>(C + (size_t)(m0 + r) * Nn + n0 + cq) = v;
    }
    if (tid < 128) {
        float s = 0.f;
        for (int cc = 0; cc < 128; cc++) s += Cs[tid * LDC + cc];
        atomicAdd(&deg[m0 + tid], s);
    }
}

__global__ void k_grow_f32(const float* __restrict__ A, int n,
                           const int* __restrict__ perm, int ksel,
                           float* __restrict__ Br) {
    size_t t = (size_t)blockIdx.x * 256 + threadIdx.x;
    if (t >= (size_t)ksel * n) return;
    int r = t / n, k = t % n;
    int pr = perm[r];
    Br[t] = (k == pr) ? 1.0f : A[(size_t)pr * n + k];
}

__global__ void k_gcol_f32(const float* __restrict__ A, int n,
                           const int* __restrict__ perm, int ksel,
                           float* __restrict__ Bc) {
    size_t t = (size_t)blockIdx.x * 256 + threadIdx.x;
    if (t >= (size_t)n * ksel) return;
    int k = t / ksel, c = t % ksel;
    int pc = perm[c];
    Bc[t] = (k == pc) ? 1.0f : A[(size_t)k * n + pc];
}

__global__ __launch_bounds__(256) void k_gemm64(const float* __restrict__ Br,
                                                const float* __restrict__ Bc,
                                                float* __restrict__ C, int K, int Nn,
                                                float* __restrict__ deg) {
    __shared__ float As[16][65];
    __shared__ float Bs[16][65];
    int tid = threadIdx.x;
    int m0 = blockIdx.y * 64, n0 = blockIdx.x * 64;
    int ty = tid >> 4, tx = tid & 15;
    float acc[4][4] = {};
    for (int k0 = 0; k0 < K; k0 += 16) {
#pragma unroll
        for (int l = 0; l < 4; l++) {
            int e = tid + 256 * l;
            int row = e >> 4, kk = e & 15;
            As[kk][row] = Br[(size_t)(m0 + row) * K + k0 + kk];
        }
#pragma unroll
        for (int l = 0; l < 4; l++) {
            int e = tid + 256 * l;
            int row = e >> 6, col = e & 63;
            Bs[row][col] = Bc[(size_t)(k0 + row) * Nn + n0 + col];
        }
        __syncthreads();
#pragma unroll
        for (int kk = 0; kk < 16; kk++) {
            float a[4], b[4];
#pragma unroll
            for (int i = 0; i < 4; i++) a[i] = As[kk][ty * 4 + i];
#pragma unroll
            for (int j = 0; j < 4; j++) b[j] = Bs[kk][tx * 4 + j];
#pragma unroll
            for (int i = 0; i < 4; i++)
#pragma unroll
                for (int j = 0; j < 4; j++) acc[i][j] = fmaf(a[i], b[j], acc[i][j]);
        }
        __syncthreads();
    }
#pragma unroll
    for (int i = 0; i < 4; i++) {
        int gr = m0 + ty * 4 + i;
        float rs = 0.f;
#pragma unroll
        for (int j = 0; j < 4; j++) {
            int gc = n0 + tx * 4 + j;
            if (gr == gc) acc[i][j] = 0.f;
            rs += acc[i][j];
            C[(size_t)gr * Nn + gc] = acc[i][j];
        }
        atomicAdd(&deg[gr], rs);
    }
}

// ---------------- misc ----------------

__global__ void k_score(const float* __restrict__ X, const float* __restrict__ w,
                        int n, int c, float* __restrict__ score) {
    int row = blockIdx.x;
    __shared__ float sh[128];
    const float* xr = X + (size_t)row * c;
    float wsq = 0.f, dot = 0.f;
    for (int k = threadIdx.x; k < c; k += 128) {
        float wv = w[k];
        wsq += wv * wv;
        dot += xr[k] * wv;
    }
    sh[threadIdx.x] = wsq;
    __syncthreads();
    for (int o = 64; o > 0; o >>= 1) {
        if (threadIdx.x < o) sh[threadIdx.x] += sh[threadIdx.x + o];
        __syncthreads();
    }
    float wn = sh[0];
    __syncthreads();
    sh[threadIdx.x] = dot;
    __syncthreads();
    for (int o = 64; o > 0; o >>= 1) {
        if (threadIdx.x < o) sh[threadIdx.x] += sh[threadIdx.x + o];
        __syncthreads();
    }
    if (threadIdx.x == 0) score[row] = tanhf(sh[0] / sqrtf(wn));
}

__global__ void k_rank(const float* __restrict__ score, int n, int k,
                       int* __restrict__ perm, float* __restrict__ vals,
                       int* __restrict__ inv) {
    __shared__ float ss[1024];
    int i = blockIdx.x * 256 + threadIdx.x;
    float si = (i < n) ? score[i] : 0.f;
    int rank = 0;
    for (int t0 = 0; t0 < n; t0 += 1024) {
#pragma unroll
        for (int l = 0; l < 4; l++) {
            int idx = threadIdx.x + 256 * l;
            int g = t0 + idx;
            ss[idx] = (g < n) ? score[g] : -1e30f;
        }
        __syncthreads();
#pragma unroll 8
        for (int jj = 0; jj < 1024; jj++) {
            float sj = ss[jj];
            int j = t0 + jj;
            rank += (sj > si) || (sj == si && j < i);
        }
        __syncthreads();
    }
    if (i >= n) return;
    if (rank < k) {
        perm[rank] = i;
        vals[rank] = si;
        inv[i] = rank;
    } else {
        inv[i] = -1;
    }
}

// ---------------- host orchestration ----------------

struct Ptrs {
    float *y, *z, *P;
    __nv_bfloat16* zc;
};

static void prop_tc(const __nv_bfloat16* Ab, int n, const float* b, int c, bool relu,
                    float* out, const float* dinv, const float* selfc, const Ptrs& q) {
    const int KS = 8;
    k_prop<<<dim3(n / 64, KS), 256, PROP_SMEM>>>(Ab, q.zc, q.P, n, KS);
    k_prop_epi<<<(n * c + 255) / 256, 256>>>(q.P, q.y, dinv, selfc, b, out, n, c, KS, relu ? 1 : 0);
}

static void prop_f32(const float* A, int n, const float* b, int c, bool relu,
                     float* out, const float* dinv, const float* selfc, const Ptrs& q) {
    const int KS = 8;
    dim3 g2((c + 31) / 32, n / 64, KS);
    k_gcnmm_sp<<<g2, 256>>>(A, q.z, q.P, n, c, KS);
    k_gcn_epi<<<(n * c + 255) / 256, 256>>>(q.P, q.y, dinv, selfc, b, out, n, c, KS, relu ? 1 : 0);
}

extern "C" void kernel_launch(void* const* d_in, const int* in_sizes, int n_in,
                              void* d_out, int out_size) {
    const float* x = (const float*)d_in[0];
    const int* ei = (const int*)d_in[1];
    const float *Wd[5], *bd[5], *p[4], *Wu[4], *bu[4];
    for (int i = 0; i < 5; i++) { Wd[i] = (const float*)d_in[2 + 2 * i]; bd[i] = (const float*)d_in[3 + 2 * i]; }
    for (int i = 0; i < 4; i++) p[i] = (const float*)d_in[12 + i];
    for (int i = 0; i < 4; i++) { Wu[i] = (const float*)d_in[16 + 2 * i]; bu[i] = (const float*)d_in[17 + 2 * i]; }
    const float* Wo = (const float*)d_in[24];
    const float* bo = (const float*)d_in[25];

    static bool attrset = false;
    if (!attrset) {
        cudaFuncSetAttribute(k_aug, cudaFuncAttributeMaxDynamicSharedMemorySize, AUG_SMEM);
        cudaFuncSetAttribute(k_prop, cudaFuncAttributeMaxDynamicSharedMemorySize, PROP_SMEM);
        attrset = true;
    }

    __nv_bfloat16 *A1b, *A1tb;
    float *C1, *A2, *A3, *A4, *xs0, *xs1, *xs2, *xs3, *xb;
    float *Brf, *Bcf, *score, *vals, *degall;
    float *di0, *sf0, *di1, *sf1, *di2, *sf2, *di3, *sf3, *di4, *sf4;
    int *pm0, *pm1, *pm2, *pm3;
    int *iv0, *iv1, *iv2, *iv3;
    int *call, *selfn, *csrc, *cdst, *offS, *offD, *headS, *headD, *outl, *inl;
    Ptrs q;
    cudaGetSymbolAddress((void**)&A1b, dA1b);
    cudaGetSymbolAddress((void**)&A1tb, dA1tb);
    cudaGetSymbolAddress((void**)&C1, dC1);
    cudaGetSymbolAddress((void**)&A2, dA2);
    cudaGetSymbolAddress((void**)&A3, dA3);
    cudaGetSymbolAddress((void**)&A4, dA4);
    cudaGetSymbolAddress((void**)&Brf, dBrf);
    cudaGetSymbolAddress((void**)&Bcf, dBcf);
    cudaGetSymbolAddress((void**)&q.P, dP);
    cudaGetSymbolAddress((void**)&xs0, dxs0);
    cudaGetSymbolAddress((void**)&xs1, dxs1);
    cudaGetSymbolAddress((void**)&xs2, dxs2);
    cudaGetSymbolAddress((void**)&xs3, dxs3);
    cudaGetSymbolAddress((void**)&xb, dxb);
    cudaGetSymbolAddress((void**)&q.y, dybuf);
    cudaGetSymbolAddress((void**)&q.z, dzbuf);
    q.zc = (__nv_bfloat16*)q.z;
    cudaGetSymbolAddress((void**)&degall, ddegall);
    cudaGetSymbolAddress((void**)&di0, dinv0); cudaGetSymbolAddress((void**)&sf0, dself0);
    cudaGetSymbolAddress((void**)&di1, dinv1); cudaGetSymbolAddress((void**)&sf1, dself1);
    cudaGetSymbolAddress((void**)&di2, dinv2); cudaGetSymbolAddress((void**)&sf2, dself2);
    cudaGetSymbolAddress((void**)&di3, dinv3); cudaGetSymbolAddress((void**)&sf3, dself3);
    cudaGetSymbolAddress((void**)&di4, dinv4); cudaGetSymbolAddress((void**)&sf4, dself4);
    cudaGetSymbolAddress((void**)&score, dscorev);
    cudaGetSymbolAddress((void**)&vals, dvalsv);
    cudaGetSymbolAddress((void**)&pm0, dperm0);
    cudaGetSymbolAddress((void**)&pm1, dperm1);
    cudaGetSymbolAddress((void**)&pm2, dperm2);
    cudaGetSymbolAddress((void**)&pm3, dperm3);
    cudaGetSymbolAddress((void**)&iv0, dinvi0);
    cudaGetSymbolAddress((void**)&iv1, dinvi1);
    cudaGetSymbolAddress((void**)&iv2, dinvi2);
    cudaGetSymbolAddress((void**)&iv3, dinvi3);
    cudaGetSymbolAddress((void**)&call, dcall);
    cudaGetSymbolAddress((void**)&selfn, dselfn);
    cudaGetSymbolAddress((void**)&csrc, dcsrc);
    cudaGetSymbolAddress((void**)&cdst, dcdst);
    cudaGetSymbolAddress((void**)&offS, doffS);
    cudaGetSymbolAddress((void**)&offD, doffD);
    cudaGetSymbolAddress((void**)&headS, dheadS);
    cudaGetSymbolAddress((void**)&headD, dheadD);
    cudaGetSymbolAddress((void**)&outl, doutl);
    cudaGetSymbolAddress((void**)&inl, dinl);

    float* degL1 = degall;
    float* degL2 = degall + 2048;
    float* degL3 = degall + 3072;
    float* degL4 = degall + 3584;

    // ---- build sparse adjacency structures ----
    k_zero<<<16, 256>>>(call, selfn, csrc, cdst, degall);
    cudaMemsetAsync(C1, 0, (size_t)2048 * 2048 * sizeof(float));
    k_ecnt<<<EDG / 256, 256>>>(ei, call, selfn, csrc, cdst);
    k_scan<<<2, 1024>>>(csrc, offS, headS, cdst, offD, headD);
    k_fill<<<EDG / 256, 256>>>(ei, headS, headD, outl, inl);
    k_degfin0<<<N0 / 256, 256>>>(call, selfn, N0, di0, sf0);

    // GCN0 (sparse)
    {
        dim3 bx(32, 8);
        k_xw<<<dim3(1, 512), bx>>>(x, Wd[0], di0, q.y, q.z, 4096, 128, 32);
        k_sprop<<<4096, 64>>>(offD, inl, selfn, q.z, q.y, di0, sf0, bd[0], xs0, 32, 1, 0);
    }

    // ---- level 1: sparse path-pair augment ----
    k_score<<<4096, 128>>>(xs0, p[0], 4096, 32, score);
    k_rank<<<16, 256>>>(score, 4096, 2048, pm0, vals, iv0);
    k_pairs<<<4096, 256>>>(offS, outl, offD, inl, iv0, C1, 2048);
    k_addA<<<EDG / 256, 256>>>(ei, iv0, C1, 2048);
    k_a1fin<<<dim3(2048 / 32, 2048 / 32), dim3(32, 8)>>>(C1, A1b, A1tb, degL1, 2048);
    k_degfin2<<<2048 / 256, 256>>>(degL1, 2048, di1, sf1);
    k_xwp_cat<<<2048 / 4, 256>>>(xs0, pm0, vals, Wd[1], di1, q.y, q.zc, 2048, 32, 64);
    prop_tc(A1b, 2048, bd[1], 64, true, xs1, di1, sf1, q);

    // ---- level 2: dense fused gather+augment ----
    k_score<<<2048, 128>>>(xs1, p[1], 2048, 64, score);
    k_rank<<<8, 256>>>(score, 2048, 1024, pm1, vals, iv1);
    k_aug<<<dim3(8, 8), 256, AUG_SMEM>>>(A1b, A1tb, pm1, 2048, 1024, A2, degL2);
    k_degfin2<<<1024 / 256, 256>>>(degL2, 1024, di2, sf2);
    {
        dim3 bx(32, 8);
        k_xwp<<<dim3(4, 128), bx>>>(xs1, pm1, vals, Wd[2], di2, q.y, q.z, 1024, 64, 128);
        prop_f32(A2, 1024, bd[2], 128, true, xs2, di2, sf2, q);
    }

    // ---- level 3 ----
    k_score<<<1024, 128>>>(xs2, p[2], 1024, 128, score);
    k_rank<<<4, 256>>>(score, 1024, 512, pm2, vals, iv2);
    k_grow_f32<<<(512 * 1024 + 255) / 256, 256>>>(A2, 1024, pm2, 512, Brf);
    k_gcol_f32<<<(1024 * 512 + 255) / 256, 256>>>(A2, 1024, pm2, 512, Bcf);
    k_gemm64<<<dim3(8, 8), 256>>>(Brf, Bcf, A3, 1024, 512, degL3);
    k_degfin2<<<512 / 256, 256>>>(degL3, 512, di3, sf3);
    {
        dim3 bx(32, 8);
        k_xwp<<<dim3(8, 64), bx>>>(xs2, pm2, vals, Wd[3], di3, q.y, q.z, 512, 128, 256);
        prop_f32(A3, 512, bd[3], 256, true, xs3, di3, sf3, q);
    }

    // ---- level 4 ----
    k_score<<<512, 128>>>(xs3, p[3], 512, 256, score);
    k_rank<<<2, 256>>>(score, 512, 256, pm3, vals, iv3);
    k_grow_f32<<<(256 * 512 + 255) / 256, 256>>>(A3, 512, pm3, 256, Brf);
    k_gcol_f32<<<(512 * 256 + 255) / 256, 256>>>(A3, 512, pm3, 256, Bcf);
    k_gemm64<<<dim3(4, 4), 256>>>(Brf, Bcf, A4, 512, 256, degL4);
    k_degfin2<<<1, 256>>>(degL4, 256, di4, sf4);
    {
        dim3 bx(32, 8);
        k_xwp<<<dim3(16, 32), bx>>>(xs3, pm3, vals, Wd[4], di4, q.y, q.z, 256, 256, 512);
        prop_f32(A4, 256, bd[4], 512, true, xb, di4, sf4, q);
    }

    // ---- up 0 ----
    {
        dim3 bx(32, 8);
        k_xwu<<<dim3(8, 64), bx>>>(xs3, 256, xb, 512, iv3, Wu[0], di3, q.y, q.z, 512, 256);
        prop_f32(A3, 512, bu[0], 256, true, xb, di3, sf3, q);
    }
    // ---- up 1 ----
    {
        dim3 bx(32, 8);
        k_xwu<<<dim3(4, 128), bx>>>(xs2, 128, xb, 256, iv2, Wu[1], di2, q.y, q.z, 1024, 128);
        prop_f32(A2, 1024, bu[1], 128, true, xb, di2, sf2, q);
    }
    // ---- up 2 (tc) ----
    k_xwu_cat<<<2048 / 4, 256>>>(xs1, 64, xb, 128, iv1, Wu[2], di1, q.y, q.zc, 2048, 64);
    prop_tc(A1b, 2048, bu[2], 64, true, xb, di1, sf1, q);

    // ---- up 3 (sparse), NO relu ----
    {
        dim3 bx(32, 8);
        k_xwu<<<dim3(1, 512), bx>>>(xs0, 32, xb, 64, iv0, Wu[3], di0, q.y, q.z, 4096, 32);
        k_sprop<<<4096, 64>>>(offD, inl, selfn, q.z, q.y, di0, sf0, bu[3], xb, 32, 0, 0);
    }

    // ---- final GCN (sparse) + fused softmax -> d_out ----
    {
        dim3 bx(32, 8);
        k_xw<<<dim3(2, 512), bx>>>(xb, Wo, di0, q.y, q.z, 4096, 32, 37);
        k_sprop<<<4096, 64>>>(offD, inl, selfn, q.z, q.y, di0, sf0, bo, (float*)d_out, 37, 0, 1);
    }
}

// round 16
// speedup vs baseline: 1.1361x; 1.0691x over previous
#include <cuda_runtime.h>
#include <cuda_bf16.h>
#include <mma.h>
#include <math.h>

using namespace nvcuda;

#define N0 4096
#define EDG 131072

// ---------------- device scratch ----------------
__device__ __nv_bfloat16 dA1b[2048 * 2048];
__device__ __nv_bfloat16 dA1tb[2048 * 2048];
__device__ float dC1[2048 * 2048];
__device__ float dA2[1024 * 1024];
__device__ float dA3[512 * 512];
__device__ float dA4[256 * 256];
__device__ float dBrf[512 * 1024];
__device__ float dBcf[1024 * 512];
__device__ float dP[8 * 4096 * 128];
__device__ float dxs0[4096 * 32];
__device__ float dxs1[2048 * 64];
__device__ float dxs2[1024 * 128];
__device__ float dxs3[512 * 256];
__device__ float dxb[4096 * 512];
__device__ float dybuf[4096 * 512];
__device__ float dzbuf[4096 * 512];
__device__ float ddegall[3840];
__device__ float dinv0[4096], dself0[4096];
__device__ float dinv1[2048], dself1[2048];
__device__ float dinv2[1024], dself2[1024];
__device__ float dinv3[512], dself3[512];
__device__ float dinv4[256], dself4[256];
__device__ float dscorev[4096];
__device__ float dvalsv[2048];
__device__ int dperm0[2048];
__device__ int dperm1[1024];
__device__ int dperm2[512];
__device__ int dperm3[256];
__device__ int dinvi0[4096];
__device__ int dinvi1[2048];
__device__ int dinvi2[1024];
__device__ int dinvi3[512];
__device__ int dcall[4096], dselfn[4096], dcsrc[4096], dcdst[4096];
__device__ int doffS[4097], doffD[4097], dheadS[4096], dheadD[4096];
__device__ int doutl[EDG], dinl[EDG];

// ---------------- helpers ----------------
__device__ __forceinline__ void cpa16(void* s, const void* g) {
    unsigned sa = (unsigned)__cvta_generic_to_shared(s);
    asm volatile("cp.async.cg.shared.global [%0], [%1], 16;\n" ::"r"(sa), "l"(g));
}
__device__ __forceinline__ void cpcommit() { asm volatile("cp.async.commit_group;\n"); }
__device__ __forceinline__ void cpwait1() { asm volatile("cp.async.wait_group 1;\n"); }

__global__ void k_zero(int* __restrict__ call, int* __restrict__ selfn,
                       int* __restrict__ csrc, int* __restrict__ cdst,
                       float* __restrict__ degall) {
    int i = blockIdx.x * 256 + threadIdx.x;
    if (i < 4096) {
        call[i] = 0;
        selfn[i] = 0;
        csrc[i] = 0;
        cdst[i] = 0;
    }
    if (i < 3840) degall[i] = 0.f;
}

// ---------------- sparse build kernels ----------------

__global__ void k_ecnt(const int* __restrict__ ei, int* __restrict__ call,
                       int* __restrict__ selfn, int* __restrict__ csrc,
                       int* __restrict__ cdst) {
    int e = blockIdx.x * 256 + threadIdx.x;
    if (e >= EDG) return;
    int s = ei[e], d = ei[EDG + e];
    atomicAdd(&call[d], 1);
    if (s == d) {
        atomicAdd(&selfn[d], 1);
    } else {
        atomicAdd(&csrc[s], 1);
        atomicAdd(&cdst[d], 1);
    }
}

__global__ void k_scan(const int* __restrict__ c0, int* __restrict__ off0, int* __restrict__ head0,
                       const int* __restrict__ c1, int* __restrict__ off1, int* __restrict__ head1) {
    const int* c = blockIdx.x ? c1 : c0;
    int* off = blockIdx.x ? off1 : off0;
    int* head = blockIdx.x ? head1 : head0;
    __shared__ int sh[1024];
    int tid = threadIdx.x;
    int base = tid * 4;
    int v0 = c[base], v1 = c[base + 1], v2 = c[base + 2], v3 = c[base + 3];
    sh[tid] = v0 + v1 + v2 + v3;
    __syncthreads();
    for (int o = 1; o < 1024; o <<= 1) {
        int x = (tid >= o) ? sh[tid - o] : 0;
        __syncthreads();
        sh[tid] += x;
        __syncthreads();
    }
    int excl = tid ? sh[tid - 1] : 0;
    int p0 = excl, p1 = excl + v0, p2 = p1 + v1, p3 = p2 + v2;
    off[base] = p0; off[base + 1] = p1; off[base + 2] = p2; off[base + 3] = p3;
    head[base] = p0; head[base + 1] = p1; head[base + 2] = p2; head[base + 3] = p3;
    if (tid == 1023) off[4096] = sh[1023];
}

__global__ void k_fill(const int* __restrict__ ei, int* __restrict__ headS,
                       int* __restrict__ headD, int* __restrict__ outl,
                       int* __restrict__ inl) {
    int e = blockIdx.x * 256 + threadIdx.x;
    if (e >= EDG) return;
    int s = ei[e], d = ei[EDG + e];
    if (s == d) return;
    int p = atomicAdd(&headS[s], 1);
    outl[p] = d;
    int q = atomicAdd(&headD[d], 1);
    inl[q] = s;
}

__global__ void k_degfin0(const int* __restrict__ call, const int* __restrict__ selfn,
                          int n, float* __restrict__ dinv, float* __restrict__ selfc) {
    int i = blockIdx.x * 256 + threadIdx.x;
    if (i >= n) return;
    float fill = (selfn[i] == 0) ? 2.0f : 0.0f;
    float d = (float)call[i] + fill;
    float di = (d > 0.f) ? (1.0f / sqrtf(d)) : 0.f;
    dinv[i] = di;
    selfc[i] = di * di * fill;
}

#define MAXD 192
__global__ void k_pairs(const int* __restrict__ offS, const int* __restrict__ outl,
                        const int* __restrict__ offD, const int* __restrict__ inl,
                        const int* __restrict__ inv, float* __restrict__ C1, int ld) {
    int k = blockIdx.x;
    __shared__ int so[MAXD], si[MAXD];
    __shared__ int cnto, cnti;
    int tid = threadIdx.x;
    if (tid == 0) { cnto = 0; cnti = 0; }
    __syncthreads();
    int b0 = offS[k], b1 = offS[k + 1];
    for (int t = b0 + tid; t < b1; t += 256) {
        int r = inv[outl[t]];
        if (r >= 0) { int p = atomicAdd(&cnto, 1); so[p] = r; }
    }
    int c0 = offD[k], c1 = offD[k + 1];
    for (int t = c0 + tid; t < c1; t += 256) {
        int r = inv[inl[t]];
        if (r >= 0) { int p = atomicAdd(&cnti, 1); si[p] = r; }
    }
    __syncthreads();
    int no = cnto, ni = cnti;
    int tot = no * ni;
    for (int t = tid; t < tot; t += 256) {
        int i = t / ni, j = t % ni;
        atomicAdd(&C1[(size_t)so[i] * ld + si[j]], 1.0f);
    }
}

__global__ void k_addA(const int* __restrict__ ei, const int* __restrict__ inv,
                       float* __restrict__ C1, int ld) {
    int e = blockIdx.x * 256 + threadIdx.x;
    if (e >= EDG) return;
    int s = ei[e], d = ei[EDG + e];
    if (s == d) return;
    int rs = inv[s], rd = inv[d];
    if (rs >= 0 && rd >= 0) atomicAdd(&C1[(size_t)rd * ld + rs], 2.0f);
}

__global__ void k_a1fin(const float* __restrict__ C1, __nv_bfloat16* __restrict__ Ab,
                        __nv_bfloat16* __restrict__ AbT, float* __restrict__ deg, int n) {
    __shared__ __nv_bfloat16 tile[32][33];
    int bx = blockIdx.x * 32, by = blockIdx.y * 32;
    int tx = threadIdx.x, ty = threadIdx.y;
    for (int r = ty; r < 32; r += 8) {
        int gi = by + r, gj = bx + tx;
        float v = (gi == gj) ? 0.f : C1[(size_t)gi * n + gj];
        __nv_bfloat16 b = __float2bfloat16(v);
        Ab[(size_t)gi * n + gj] = b;
        tile[r][tx] = b;
    }
    __syncthreads();
    for (int r = ty; r < 32; r += 8)
        AbT[(size_t)(bx + r) * n + by + tx] = tile[tx][r];
    if (ty == 0) {
        float s = 0.f;
        for (int c = 0; c < 32; c++) s += __bfloat162float(tile[tx][c]);
        atomicAdd(&deg[by + tx], s);
    }
}

__global__ void k_degfin2(const float* __restrict__ deg, int n,
                          float* __restrict__ dinv, float* __restrict__ selfc) {
    int i = blockIdx.x * 256 + threadIdx.x;
    if (i >= n) return;
    float d = deg[i] + 2.0f;
    float di = (d > 0.f) ? (1.0f / sqrtf(d)) : 0.f;
    dinv[i] = di;
    selfc[i] = di * di * 2.0f;
}

__global__ void k_sprop(const int* __restrict__ offD, const int* __restrict__ inl,
                        const int* __restrict__ selfn, const float* __restrict__ Z,
                        const float* __restrict__ Y, const float* __restrict__ dinv,
                        const float* __restrict__ selfc, const float* __restrict__ bias,
                        float* __restrict__ O, int c, int dorelu, int dosm) {
    __shared__ float srow[64];
    __shared__ float smx, ssum;
    int d = blockIdx.x;
    int j = threadIdx.x;
    bool act = (j < c);
    float o = 0.f;
    if (act) {
        int b0 = offD[d], b1 = offD[d + 1];
        float acc = 0.f;
        for (int t = b0; t < b1; t++) acc += Z[(size_t)inl[t] * c + j];
        int sn = selfn[d];
        if (sn) acc += (float)sn * Z[(size_t)d * c + j];
        o = dinv[d] * acc + selfc[d] * Y[(size_t)d * c + j] + bias[j];
        if (dorelu) o = fmaxf(o, 0.f);
    }
    if (!dosm) {
        if (act) O[(size_t)d * c + j] = o;
        return;
    }
    srow[j] = act ? o : -1e30f;
    __syncthreads();
    if (j == 0) {
        float m = -1e30f;
        for (int t = 0; t < c; t++) m = fmaxf(m, srow[t]);
        float s = 0.f;
        for (int t = 0; t < c; t++) s += expf(srow[t] - m);
        smx = m;
        ssum = s;
    }
    __syncthreads();
    if (act) O[(size_t)d * c + j] = expf(o - smx) / ssum;
}

// ---------------- XW variants ----------------

__global__ void k_xw(const float* __restrict__ X, const float* __restrict__ W,
                     const float* __restrict__ dinv,
                     float* __restrict__ Y, float* __restrict__ Z,
                     int n, int cin, int cout) {
    int j = blockIdx.x * 32 + threadIdx.x;
    int i = blockIdx.y * 8 + threadIdx.y;
    if (i >= n || j >= cout) return;
    const float* xr = X + (size_t)i * cin;
    float acc = 0.f;
    for (int k = 0; k < cin; k++) acc = fmaf(xr[k], W[(size_t)k * cout + j], acc);
    Y[(size_t)i * cout + j] = acc;
    Z[(size_t)i * cout + j] = acc * dinv[i];
}

__global__ void k_xwp(const float* __restrict__ X, const int* __restrict__ perm,
                      const float* __restrict__ vals, const float* __restrict__ W,
                      const float* __restrict__ dinv,
                      float* __restrict__ Y, float* __restrict__ Z,
                      int n, int cin, int cout) {
    int j = blockIdx.x * 32 + threadIdx.x;
    int i = blockIdx.y * 8 + threadIdx.y;
    if (i >= n || j >= cout) return;
    const float* xr = X + (size_t)perm[i] * cin;
    float acc = 0.f;
    for (int k = 0; k < cin; k++) acc = fmaf(xr[k], W[(size_t)k * cout + j], acc);
    acc *= vals[i];
    Y[(size_t)i * cout + j] = acc;
    Z[(size_t)i * cout + j] = acc * dinv[i];
}

__global__ void k_xwu(const float* __restrict__ R, int c0,
                      const float* __restrict__ Xup, int sup,
                      const int* __restrict__ inv, const float* __restrict__ W,
                      const float* __restrict__ dinv,
                      float* __restrict__ Y, float* __restrict__ Z,
                      int n, int cout) {
    int j = blockIdx.x * 32 + threadIdx.x;
    int i = blockIdx.y * 8 + threadIdx.y;
    if (i >= n || j >= cout) return;
    const float* rr = R + (size_t)i * c0;
    float acc = 0.f;
    for (int k = 0; k < c0; k++) acc = fmaf(rr[k], W[(size_t)k * cout + j], acc);
    int r = inv[i];
    if (r >= 0) {
        const float* xr = Xup + (size_t)r * sup;
        for (int k = 0; k < c0; k++)
            acc = fmaf(xr[k], W[(size_t)(c0 + k) * cout + j], acc);
    }
    Y[(size_t)i * cout + j] = acc;
    Z[(size_t)i * cout + j] = acc * dinv[i];
}

__global__ void k_xwp_cat(const float* __restrict__ X, const int* __restrict__ perm,
                          const float* __restrict__ vals, const float* __restrict__ W,
                          const float* __restrict__ dinv, float* __restrict__ Y,
                          __nv_bfloat16* __restrict__ Zc, int n, int cin, int c) {
    int j = threadIdx.x & 63;
    int i = blockIdx.x * 4 + (threadIdx.x >> 6);
    if (i >= n) return;
    __nv_bfloat16 hb = __float2bfloat16(0.f), lb = hb;
    if (j < c) {
        const float* xr = X + (size_t)perm[i] * cin;
        float acc = 0.f;
        for (int k = 0; k < cin; k++) acc = fmaf(xr[k], W[(size_t)k * c + j], acc);
        acc *= vals[i];
        Y[(size_t)i * c + j] = acc;
        float z = acc * dinv[i];
        hb = __float2bfloat16(z);
        lb = __float2bfloat16(z - __bfloat162float(hb));
    }
    Zc[(size_t)i * 128 + j] = hb;
    Zc[(size_t)i * 128 + 64 + j] = lb;
}

__global__ void k_xwu_cat(const float* __restrict__ R, int c0,
                          const float* __restrict__ Xup, int sup,
                          const int* __restrict__ inv, const float* __restrict__ W,
                          const float* __restrict__ dinv, float* __restrict__ Y,
                          __nv_bfloat16* __restrict__ Zc, int n, int c) {
    int j = threadIdx.x & 63;
    int i = blockIdx.x * 4 + (threadIdx.x >> 6);
    if (i >= n) return;
    __nv_bfloat16 hb = __float2bfloat16(0.f), lb = hb;
    if (j < c) {
        const float* rr = R + (size_t)i * c0;
        float acc = 0.f;
        for (int k = 0; k < c0; k++) acc = fmaf(rr[k], W[(size_t)k * c + j], acc);
        int r = inv[i];
        if (r >= 0) {
            const float* xr = Xup + (size_t)r * sup;
            for (int k = 0; k < c0; k++)
                acc = fmaf(xr[k], W[(size_t)(c0 + k) * c + j], acc);
        }
        Y[(size_t)i * c + j] = acc;
        float z = acc * dinv[i];
        hb = __float2bfloat16(z);
        lb = __float2bfloat16(z - __bfloat162float(hb));
    }
    Zc[(size_t)i * 128 + j] = hb;
    Zc[(size_t)i * 128 + 64 + j] = lb;
}

// ---------------- dense propagation (double-buffered, hi+lo folded) ----------------
#define PROP_SMEM (2 * (64 * 72 + 64 * 136) * 2)
__global__ __launch_bounds__(256) void k_prop(const __nv_bfloat16* __restrict__ A,
                                              const __nv_bfloat16* __restrict__ Zc,
                                              float* __restrict__ P, int n, int KS) {
    extern __shared__ __nv_bfloat16 psm[];
    __nv_bfloat16* Asb = psm;
    __nv_bfloat16* Zsb = psm + 2 * 64 * 72;
    int tid = threadIdx.x;
    int warp = tid >> 5;
    int wm = warp >> 2, wn = warp & 3;
    int m0 = blockIdx.x * 64;
    int ks = blockIdx.y;
    int chunk = n / KS;
    int kbeg = ks * chunk;
    int nIter = chunk >> 6;

    auto load = [&](int b, int k0) {
        __nv_bfloat16* as = Asb + b * 64 * 72;
        __nv_bfloat16* zs = Zsb + b * 64 * 136;
#pragma unroll
        for (int l = 0; l < 2; l++) {
            int e = tid + 256 * l;
            int r = e >> 3, cg = (e & 7) * 8;
            cpa16(as + r * 72 + cg, A + (size_t)(m0 + r) * n + k0 + cg);
        }
#pragma unroll
        for (int l = 0; l < 4; l++) {
            int e = tid + 256 * l;
            int r = e >> 4, cg = (e & 15) * 8;
            cpa16(zs + r * 136 + cg, Zc + (size_t)(k0 + r) * 128 + cg);
        }
        cpcommit();
    };

    wmma::fragment<wmma::accumulator, 16, 16, 16, float> acc[2][2];
#pragma unroll
    for (int i = 0; i < 2; i++)
#pragma unroll
        for (int j = 0; j < 2; j++) wmma::fill_fragment(acc[i][j], 0.f);

    load(0, kbeg);
    for (int it = 0; it < nIter; it++) {
        int cur = it & 1;
        if (it + 1 < nIter) load(cur ^ 1, kbeg + (it + 1) * 64);
        else cpcommit();
        cpwait1();
        __syncthreads();
        __nv_bfloat16* as = Asb + cur * 64 * 72;
        __nv_bfloat16* zs = Zsb + cur * 64 * 136;
#pragma unroll
        for (int kk = 0; kk < 64; kk += 16) {
            wmma::fragment<wmma::matrix_a, 16, 16, 16, __nv_bfloat16, wmma::row_major> af[2];
            wmma::fragment<wmma::matrix_b, 16, 16, 16, __nv_bfloat16, wmma::row_major> bf[2];
#pragma unroll
            for (int i = 0; i < 2; i++)
                wmma::load_matrix_sync(af[i], as + (wm * 32 + 16 * i) * 72 + kk, 72);
#pragma unroll
            for (int j = 0; j < 2; j++)
                wmma::load_matrix_sync(bf[j], zs + kk * 136 + wn * 32 + 16 * j, 136);
#pragma unroll
            for (int i = 0; i < 2; i++)
#pragma unroll
                for (int j = 0; j < 2; j++)
                    wmma::mma_sync(acc[i][j], af[i], bf[j], acc[i][j]);
        }
        __syncthreads();
    }
    float* Cs = reinterpret_cast<float*>(psm);
    const int LDC = 132;
#pragma unroll
    for (int i = 0; i < 2; i++)
#pragma unroll
        for (int j = 0; j < 2; j++)
            wmma::store_matrix_sync(Cs + (wm * 32 + 16 * i) * LDC + wn * 32 + 16 * j,
                                    acc[i][j], LDC, wmma::mem_row_major);
    __syncthreads();
#pragma unroll
    for (int l = 0; l < 16; l++) {
        int e = tid + 256 * l;
        int r = e >> 6, c = e & 63;
        P[((size_t)ks * n + m0 + r) * 64 + c] = Cs[r * LDC + c] + Cs[r * LDC + 64 + c];
    }
}

__global__ void k_prop_epi(const float* __restrict__ P, const float* __restrict__ Y,
                           const float* __restrict__ dinv, const float* __restrict__ selfc,
                           const float* __restrict__ bias, float* __restrict__ O,
                           int n, int c, int KS, int dorelu) {
    int t = blockIdx.x * 256 + threadIdx.x;
    if (t >= n * c) return;
    int i = t / c, j = t % c;
    float s = 0.f;
    for (int ks = 0; ks < KS; ks++) s += P[((size_t)ks * n + i) * 64 + j];
    float o = dinv[i] * s + selfc[i] * Y[t] + bias[j];
    if (dorelu) o = fmaxf(o, 0.f);
    O[t] = o;
}

// fp32 split-K propagation + epilogue
__global__ __launch_bounds__(256) void k_gcnmm_sp(
    const float* __restrict__ A, const float* __restrict__ Z,
    float* __restrict__ P, int n, int c, int KS) {
    __shared__ float As[32][65];
    __shared__ float Zs[32][32];
    int tid = threadIdx.x;
    int m0 = blockIdx.y * 64;
    int n0c = blockIdx.x * 32;
    int ks = blockIdx.z;
    int chunk = n / KS;
    int kbeg = ks * chunk, kend = kbeg + chunk;
    int r0 = tid >> 5, colt = tid & 31;
    float acc[8] = {0, 0, 0, 0, 0, 0, 0, 0};
    for (int k0 = kbeg; k0 < kend; k0 += 32) {
#pragma unroll
        for (int l = 0; l < 2; l++) {
            int e = tid + 256 * l;
            int row = e >> 3, qc = (e & 7) * 4;
            float4 v = *reinterpret_cast<const float4*>(A + (size_t)(m0 + row) * n + k0 + qc);
            As[qc + 0][row] = v.x; As[qc + 1][row] = v.y;
            As[qc + 2][row] = v.z; As[qc + 3][row] = v.w;
        }
        {
            int row = tid >> 3, qc = (tid & 7) * 4;
            int gk = k0 + row;
#pragma unroll
            for (int u = 0; u < 4; u++) {
                int gc = n0c + qc + u;
                Zs[row][qc + u] = (gc < c) ? Z[(size_t)gk * c + gc] : 0.f;
            }
        }
        __syncthreads();
#pragma unroll
        for (int k = 0; k < 32; k++) {
            float zv = Zs[k][colt];
#pragma unroll
            for (int u = 0; u < 8; u++) acc[u] = fmaf(As[k][r0 + 8 * u], zv, acc[u]);
        }
        __syncthreads();
    }
    int gc = n0c + colt;
    if (gc < c) {
#pragma unroll
        for (int u = 0; u < 8; u++) {
            int gi = m0 + r0 + 8 * u;
            P[((size_t)ks * n + gi) * c + gc] = acc[u];
        }
    }
}

__global__ void k_gcn_epi(const float* __restrict__ P, const float* __restrict__ Y,
                          const float* __restrict__ dinv, const float* __restrict__ selfc,
                          const float* __restrict__ bias, float* __restrict__ O,
                          int n, int c, int KS, int dorelu) {
    int t = blockIdx.x * 256 + threadIdx.x;
    if (t >= n * c) return;
    int i = t / c, j = t % c;
    float s = 0.f;
    size_t stride = (size_t)n * c;
    for (int ks = 0; ks < KS; ks++) s += P[ks * stride + t];
    float o = dinv[i] * s + selfc[i] * Y[t] + bias[j];
    if (dorelu) o = fmaxf(o, 0.f);
    O[t] = o;
}

// ---- fused gather + augment GEMM (WMMA, 3-stage cp.async) — L2 ----
#define AUG_SMEM (3 * 2 * 128 * 72 * 2)
__global__ __launch_bounds__(256) void k_aug(const __nv_bfloat16* __restrict__ A,
                                             const __nv_bfloat16* __restrict__ AT,
                                             const int* __restrict__ permv,
                                             int K, int Nn, float* __restrict__ C,
                                             float* __restrict__ deg) {
    extern __shared__ char smraw[];
    __nv_bfloat16* AsB = reinterpret_cast<__nv_bfloat16*>(smraw);
    __nv_bfloat16* BsB = AsB + 3 * 128 * 72;
    __shared__ int spa[128], spb[128];
    const int LDK = 72;
    int tid = threadIdx.x;
    int warp = tid >> 5;
    int wm = warp >> 2, wn = warp & 3;
    int m0 = blockIdx.y * 128, n0 = blockIdx.x * 128;

    if (tid < 128) spa[tid] = permv[m0 + tid];
    else spb[tid - 128] = permv[n0 + tid - 128];
    __syncthreads();

    auto load_tiles = [&](int st, int k0) {
        __nv_bfloat16* as = AsB + st * 128 * LDK;
        __nv_bfloat16* bs = BsB + st * 128 * LDK;
#pragma unroll
        for (int l = 0; l < 4; l++) {
            int e = tid + 256 * l;
            int r = e >> 3, cg = (e & 7) * 8;
            cpa16(as + r * LDK + cg, A + (size_t)spa[r] * K + k0 + cg);
            cpa16(bs + r * LDK + cg, AT + (size_t)spb[r] * K + k0 + cg);
        }
        cpcommit();
    };

    wmma::fragment<wmma::accumulator, 16, 16, 16, float> acc[4][2];
#pragma unroll
    for (int i = 0; i < 4; i++)
#pragma unroll
        for (int j = 0; j < 2; j++) wmma::fill_fragment(acc[i][j], 0.f);

    int nIter = K / 64;
    load_tiles(0, 0);
    load_tiles(1, 64);
    for (int it = 0; it < nIter; it++) {
        int st = it % 3;
        cpwait1();
        __syncthreads();
        int k0 = it * 64;
        if (tid < 128) {
            int d = spa[tid] - k0;
            if (d >= 0 && d < 64) AsB[st * 128 * LDK + tid * LDK + d] = __float2bfloat16(1.f);
        } else {
            int r = tid - 128;
            int d = spb[r] - k0;
            if (d >= 0 && d < 64) BsB[st * 128 * LDK + r * LDK + d] = __float2bfloat16(1.f);
        }
        __syncthreads();
        if (it + 2 < nIter) load_tiles((it + 2) % 3, (it + 2) * 64);
        __nv_bfloat16* as = AsB + st * 128 * LDK;
        __nv_bfloat16* bs = BsB + st * 128 * LDK;
#pragma unroll
        for (int kk = 0; kk < 64; kk += 16) {
            wmma::fragment<wmma::matrix_a, 16, 16, 16, __nv_bfloat16, wmma::row_major> af[4];
            wmma::fragment<wmma::matrix_b, 16, 16, 16, __nv_bfloat16, wmma::col_major> bf[2];
#pragma unroll
            for (int i = 0; i < 4; i++)
                wmma::load_matrix_sync(af[i], as + (wm * 64 + 16 * i) * LDK + kk, LDK);
#pragma unroll
            for (int j = 0; j < 2; j++)
                wmma::load_matrix_sync(bf[j], bs + (wn * 32 + 16 * j) * LDK + kk, LDK);
#pragma unroll
            for (int i = 0; i < 4; i++)
#pragma unroll
                for (int j = 0; j < 2; j++)
                    wmma::mma_sync(acc[i][j], af[i], bf[j], acc[i][j]);
        }
    }
    __syncthreads();
    float* Cs = reinterpret_cast<float*>(smraw);
    const int LDC = 132;
#pragma unroll
    for (int i = 0; i < 4; i++)
#pragma unroll
        for (int j = 0; j < 2; j++)
            wmma::store_matrix_sync(Cs + (wm * 64 + 16 * i) * LDC + wn * 32 + 16 * j,
                                    acc[i][j], LDC, wmma::mem_row_major);
    __syncthreads();
    if (m0 == n0 && tid < 128) Cs[tid * LDC + tid] = 0.f;
    __syncthreads();
#pragma unroll
    for (int l = 0; l < 16; l++) {
        int e = tid + 256 * l;
        int r = e >> 5, cq = (e & 31) * 4;
        float4 v;
        v.x = Cs[r * LDC + cq];
        v.y = Cs[r * LDC + cq + 1];
        v.z = Cs[r * LDC + cq + 2];
        v.w = Cs[r * LDC + cq + 3];
        *reinterpret_cast<float4*>(C + (size_t)(m0 + r) * Nn + n0 + cq) = v;
    }
    if (tid < 128) {
        float s = 0.f;
        for (int cc = 0; cc < 128; cc++) s += Cs[tid * LDC + cc];
        atomicAdd(&deg[m0 + tid], s);
    }
}

__global__ void k_grow_f32(const float* __restrict__ A, int n,
                           const int* __restrict__ perm, int ksel,
                           float* __restrict__ Br) {
    size_t t = (size_t)blockIdx.x * 256 + threadIdx.x;
    if (t >= (size_t)ksel * n) return;
    int r = t / n, k = t % n;
    int pr = perm[r];
    Br[t] = (k == pr) ? 1.0f : A[(size_t)pr * n + k];
}

__global__ void k_gcol_f32(const float* __restrict__ A, int n,
                           const int* __restrict__ perm, int ksel,
                           float* __restrict__ Bc) {
    size_t t = (size_t)blockIdx.x * 256 + threadIdx.x;
    if (t >= (size_t)n * ksel) return;
    int k = t / ksel, c = t % ksel;
    int pc = perm[c];
    Bc[t] = (k == pc) ? 1.0f : A[(size_t)k * n + pc];
}

// double-buffered fp32 SGEMM (BM=64, BN=64, BK=32, cp.async 2-stage)
// with fused diag-zero + deg row sums
__global__ __launch_bounds__(256) void k_gemm64(const float* __restrict__ Br,
                                                const float* __restrict__ Bc,
                                                float* __restrict__ C, int K, int Nn,
                                                float* __restrict__ deg) {
    __shared__ float As[2][64][36];
    __shared__ float Bs[2][32][68];
    int tid = threadIdx.x;
    int m0 = blockIdx.y * 64, n0 = blockIdx.x * 64;
    int ty = tid >> 4, tx = tid & 15;
    float acc[4][4] = {};

    auto load = [&](int b, int k0) {
#pragma unroll
        for (int l = 0; l < 2; l++) {
            int e = tid + 256 * l;
            int row = e >> 3, sg = (e & 7) * 4;
            cpa16(&As[b][row][sg], Br + (size_t)(m0 + row) * K + k0 + sg);
        }
#pragma unroll
        for (int l = 0; l < 2; l++) {
            int e = tid + 256 * l;
            int kk = e >> 4, cl = (e & 15) * 4;
            cpa16(&Bs[b][kk][cl], Bc + (size_t)(k0 + kk) * Nn + n0 + cl);
        }
        cpcommit();
    };

    int nIter = K / 32;
    load(0, 0);
    for (int it = 0; it < nIter; it++) {
        int cur = it & 1;
        if (it + 1 < nIter) load(cur ^ 1, (it + 1) * 32);
        else cpcommit();
        cpwait1();
        __syncthreads();
#pragma unroll 8
        for (int kk = 0; kk < 32; kk++) {
            float a[4], b[4];
#pragma unroll
            for (int i = 0; i < 4; i++) a[i] = As[cur][ty * 4 + i][kk];
#pragma unroll
            for (int j = 0; j < 4; j++) b[j] = Bs[cur][kk][tx * 4 + j];
#pragma unroll
            for (int i = 0; i < 4; i++)
#pragma unroll
                for (int j = 0; j < 4; j++) acc[i][j] = fmaf(a[i], b[j], acc[i][j]);
        }
        __syncthreads();
    }
#pragma unroll
    for (int i = 0; i < 4; i++) {
        int gr = m0 + ty * 4 + i;
        float rs = 0.f;
#pragma unroll
        for (int j = 0; j < 4; j++) {
            int gc = n0 + tx * 4 + j;
            if (gr == gc) acc[i][j] = 0.f;
            rs += acc[i][j];
            C[(size_t)gr * Nn + gc] = acc[i][j];
        }
        atomicAdd(&deg[gr], rs);
    }
}

// ---------------- misc ----------------

__global__ void k_score(const float* __restrict__ X, const float* __restrict__ w,
                        int n, int c, float* __restrict__ score) {
    int row = blockIdx.x;
    __shared__ float sh[128];
    const float* xr = X + (size_t)row * c;
    float wsq = 0.f, dot = 0.f;
    for (int k = threadIdx.x; k < c; k += 128) {
        float wv = w[k];
        wsq += wv * wv;
        dot += xr[k] * wv;
    }
    sh[threadIdx.x] = wsq;
    __syncthreads();
    for (int o = 64; o > 0; o >>= 1) {
        if (threadIdx.x < o) sh[threadIdx.x] += sh[threadIdx.x + o];
        __syncthreads();
    }
    float wn = sh[0];
    __syncthreads();
    sh[threadIdx.x] = dot;
    __syncthreads();
    for (int o = 64; o > 0; o >>= 1) {
        if (threadIdx.x < o) sh[threadIdx.x] += sh[threadIdx.x + o];
        __syncthreads();
    }
    if (threadIdx.x == 0) score[row] = tanhf(sh[0] / sqrtf(wn));
}

__global__ void k_rank(const float* __restrict__ score, int n, int k,
                       int* __restrict__ perm, float* __restrict__ vals,
                       int* __restrict__ inv) {
    __shared__ float ss[1024];
    int i = blockIdx.x * 256 + threadIdx.x;
    float si = (i < n) ? score[i] : 0.f;
    int rank = 0;
    for (int t0 = 0; t0 < n; t0 += 1024) {
#pragma unroll
        for (int l = 0; l < 4; l++) {
            int idx = threadIdx.x + 256 * l;
            int g = t0 + idx;
            ss[idx] = (g < n) ? score[g] : -1e30f;
        }
        __syncthreads();
#pragma unroll 8
        for (int jj = 0; jj < 1024; jj++) {
            float sj = ss[jj];
            int j = t0 + jj;
            rank += (sj > si) || (sj == si && j < i);
        }
        __syncthreads();
    }
    if (i >= n) return;
    if (rank < k) {
        perm[rank] = i;
        vals[rank] = si;
        inv[i] = rank;
    } else {
        inv[i] = -1;
    }
}

// ---------------- host orchestration ----------------

struct Ptrs {
    float *y, *z, *P;
    __nv_bfloat16* zc;
};

static void prop_tc(const __nv_bfloat16* Ab, int n, const float* b, int c, bool relu,
                    float* out, const float* dinv, const float* selfc, const Ptrs& q) {
    const int KS = 8;
    k_prop<<<dim3(n / 64, KS), 256, PROP_SMEM>>>(Ab, q.zc, q.P, n, KS);
    k_prop_epi<<<(n * c + 255) / 256, 256>>>(q.P, q.y, dinv, selfc, b, out, n, c, KS, relu ? 1 : 0);
}

static void prop_f32(const float* A, int n, const float* b, int c, bool relu,
                     float* out, const float* dinv, const float* selfc, const Ptrs& q) {
    const int KS = 8;
    dim3 g2((c + 31) / 32, n / 64, KS);
    k_gcnmm_sp<<<g2, 256>>>(A, q.z, q.P, n, c, KS);
    k_gcn_epi<<<(n * c + 255) / 256, 256>>>(q.P, q.y, dinv, selfc, b, out, n, c, KS, relu ? 1 : 0);
}

extern "C" void kernel_launch(void* const* d_in, const int* in_sizes, int n_in,
                              void* d_out, int out_size) {
    const float* x = (const float*)d_in[0];
    const int* ei = (const int*)d_in[1];
    const float *Wd[5], *bd[5], *p[4], *Wu[4], *bu[4];
    for (int i = 0; i < 5; i++) { Wd[i] = (const float*)d_in[2 + 2 * i]; bd[i] = (const float*)d_in[3 + 2 * i]; }
    for (int i = 0; i < 4; i++) p[i] = (const float*)d_in[12 + i];
    for (int i = 0; i < 4; i++) { Wu[i] = (const float*)d_in[16 + 2 * i]; bu[i] = (const float*)d_in[17 + 2 * i]; }
    const float* Wo = (const float*)d_in[24];
    const float* bo = (const float*)d_in[25];

    static bool attrset = false;
    if (!attrset) {
        cudaFuncSetAttribute(k_aug, cudaFuncAttributeMaxDynamicSharedMemorySize, AUG_SMEM);
        cudaFuncSetAttribute(k_prop, cudaFuncAttributeMaxDynamicSharedMemorySize, PROP_SMEM);
        attrset = true;
    }

    __nv_bfloat16 *A1b, *A1tb;
    float *C1, *A2, *A3, *A4, *xs0, *xs1, *xs2, *xs3, *xb;
    float *Brf, *Bcf, *score, *vals, *degall;
    float *di0, *sf0, *di1, *sf1, *di2, *sf2, *di3, *sf3, *di4, *sf4;
    int *pm0, *pm1, *pm2, *pm3;
    int *iv0, *iv1, *iv2, *iv3;
    int *call, *selfn, *csrc, *cdst, *offS, *offD, *headS, *headD, *outl, *inl;
    Ptrs q;
    cudaGetSymbolAddress((void**)&A1b, dA1b);
    cudaGetSymbolAddress((void**)&A1tb, dA1tb);
    cudaGetSymbolAddress((void**)&C1, dC1);
    cudaGetSymbolAddress((void**)&A2, dA2);
    cudaGetSymbolAddress((void**)&A3, dA3);
    cudaGetSymbolAddress((void**)&A4, dA4);
    cudaGetSymbolAddress((void**)&Brf, dBrf);
    cudaGetSymbolAddress((void**)&Bcf, dBcf);
    cudaGetSymbolAddress((void**)&q.P, dP);
    cudaGetSymbolAddress((void**)&xs0, dxs0);
    cudaGetSymbolAddress((void**)&xs1, dxs1);
    cudaGetSymbolAddress((void**)&xs2, dxs2);
    cudaGetSymbolAddress((void**)&xs3, dxs3);
    cudaGetSymbolAddress((void**)&xb, dxb);
    cudaGetSymbolAddress((void**)&q.y, dybuf);
    cudaGetSymbolAddress((void**)&q.z, dzbuf);
    q.zc = (__nv_bfloat16*)q.z;
    cudaGetSymbolAddress((void**)&degall, ddegall);
    cudaGetSymbolAddress((void**)&di0, dinv0); cudaGetSymbolAddress((void**)&sf0, dself0);
    cudaGetSymbolAddress((void**)&di1, dinv1); cudaGetSymbolAddress((void**)&sf1, dself1);
    cudaGetSymbolAddress((void**)&di2, dinv2); cudaGetSymbolAddress((void**)&sf2, dself2);
    cudaGetSymbolAddress((void**)&di3, dinv3); cudaGetSymbolAddress((void**)&sf3, dself3);
    cudaGetSymbolAddress((void**)&di4, dinv4); cudaGetSymbolAddress((void**)&sf4, dself4);
    cudaGetSymbolAddress((void**)&score, dscorev);
    cudaGetSymbolAddress((void**)&vals, dvalsv);
    cudaGetSymbolAddress((void**)&pm0, dperm0);
    cudaGetSymbolAddress((void**)&pm1, dperm1);
    cudaGetSymbolAddress((void**)&pm2, dperm2);
    cudaGetSymbolAddress((void**)&pm3, dperm3);
    cudaGetSymbolAddress((void**)&iv0, dinvi0);
    cudaGetSymbolAddress((void**)&iv1, dinvi1);
    cudaGetSymbolAddress((void**)&iv2, dinvi2);
    cudaGetSymbolAddress((void**)&iv3, dinvi3);
    cudaGetSymbolAddress((void**)&call, dcall);
    cudaGetSymbolAddress((void**)&selfn, dselfn);
    cudaGetSymbolAddress((void**)&csrc, dcsrc);
    cudaGetSymbolAddress((void**)&cdst, dcdst);
    cudaGetSymbolAddress((void**)&offS, doffS);
    cudaGetSymbolAddress((void**)&offD, doffD);
    cudaGetSymbolAddress((void**)&headS, dheadS);
    cudaGetSymbolAddress((void**)&headD, dheadD);
    cudaGetSymbolAddress((void**)&outl, doutl);
    cudaGetSymbolAddress((void**)&inl, dinl);

    float* degL1 = degall;
    float* degL2 = degall + 2048;
    float* degL3 = degall + 3072;
    float* degL4 = degall + 3584;

    // ---- build sparse adjacency structures ----
    k_zero<<<16, 256>>>(call, selfn, csrc, cdst, degall);
    cudaMemsetAsync(C1, 0, (size_t)2048 * 2048 * sizeof(float));
    k_ecnt<<<EDG / 256, 256>>>(ei, call, selfn, csrc, cdst);
    k_scan<<<2, 1024>>>(csrc, offS, headS, cdst, offD, headD);
    k_fill<<<EDG / 256, 256>>>(ei, headS, headD, outl, inl);
    k_degfin0<<<N0 / 256, 256>>>(call, selfn, N0, di0, sf0);

    // GCN0 (sparse)
    {
        dim3 bx(32, 8);
        k_xw<<<dim3(1, 512), bx>>>(x, Wd[0], di0, q.y, q.z, 4096, 128, 32);
        k_sprop<<<4096, 64>>>(offD, inl, selfn, q.z, q.y, di0, sf0, bd[0], xs0, 32, 1, 0);
    }

    // ---- level 1: sparse path-pair augment ----
    k_score<<<4096, 128>>>(xs0, p[0], 4096, 32, score);
    k_rank<<<16, 256>>>(score, 4096, 2048, pm0, vals, iv0);
    k_pairs<<<4096, 256>>>(offS, outl, offD, inl, iv0, C1, 2048);
    k_addA<<<EDG / 256, 256>>>(ei, iv0, C1, 2048);
    k_a1fin<<<dim3(2048 / 32, 2048 / 32), dim3(32, 8)>>>(C1, A1b, A1tb, degL1, 2048);
    k_degfin2<<<2048 / 256, 256>>>(degL1, 2048, di1, sf1);
    k_xwp_cat<<<2048 / 4, 256>>>(xs0, pm0, vals, Wd[1], di1, q.y, q.zc, 2048, 32, 64);
    prop_tc(A1b, 2048, bd[1], 64, true, xs1, di1, sf1, q);

    // ---- level 2: dense fused gather+augment ----
    k_score<<<2048, 128>>>(xs1, p[1], 2048, 64, score);
    k_rank<<<8, 256>>>(score, 2048, 1024, pm1, vals, iv1);
    k_aug<<<dim3(8, 8), 256, AUG_SMEM>>>(A1b, A1tb, pm1, 2048, 1024, A2, degL2);
    k_degfin2<<<1024 / 256, 256>>>(degL2, 1024, di2, sf2);
    {
        dim3 bx(32, 8);
        k_xwp<<<dim3(4, 128), bx>>>(xs1, pm1, vals, Wd[2], di2, q.y, q.z, 1024, 64, 128);
        prop_f32(A2, 1024, bd[2], 128, true, xs2, di2, sf2, q);
    }

    // ---- level 3 ----
    k_score<<<1024, 128>>>(xs2, p[2], 1024, 128, score);
    k_rank<<<4, 256>>>(score, 1024, 512, pm2, vals, iv2);
    k_grow_f32<<<(512 * 1024 + 255) / 256, 256>>>(A2, 1024, pm2, 512, Brf);
    k_gcol_f32<<<(1024 * 512 + 255) / 256, 256>>>(A2, 1024, pm2, 512, Bcf);
    k_gemm64<<<dim3(8, 8), 256>>>(Brf, Bcf, A3, 1024, 512, degL3);
    k_degfin2<<<512 / 256, 256>>>(degL3, 512, di3, sf3);
    {
        dim3 bx(32, 8);
        k_xwp<<<dim3(8, 64), bx>>>(xs2, pm2, vals, Wd[3], di3, q.y, q.z, 512, 128, 256);
        prop_f32(A3, 512, bd[3], 256, true, xs3, di3, sf3, q);
    }

    // ---- level 4 ----
    k_score<<<512, 128>>>(xs3, p[3], 512, 256, score);
    k_rank<<<2, 256>>>(score, 512, 256, pm3, vals, iv3);
    k_grow_f32<<<(256 * 512 + 255) / 256, 256>>>(A3, 512, pm3, 256, Brf);
    k_gcol_f32<<<(512 * 256 + 255) / 256, 256>>>(A3, 512, pm3, 256, Bcf);
    k_gemm64<<<dim3(4, 4), 256>>>(Brf, Bcf, A4, 512, 256, degL4);
    k_degfin2<<<1, 256>>>(degL4, 256, di4, sf4);
    {
        dim3 bx(32, 8);
        k_xwp<<<dim3(16, 32), bx>>>(xs3, pm3, vals, Wd[4], di4, q.y, q.z, 256, 256, 512);
        prop_f32(A4, 256, bd[4], 512, true, xb, di4, sf4, q);
    }

    // ---- up 0 ----
    {
        dim3 bx(32, 8);
        k_xwu<<<dim3(8, 64), bx>>>(xs3, 256, xb, 512, iv3, Wu[0], di3, q.y, q.z, 512, 256);
        prop_f32(A3, 512, bu[0], 256, true, xb, di3, sf3, q);
    }
    // ---- up 1 ----
    {
        dim3 bx(32, 8);
        k_xwu<<<dim3(4, 128), bx>>>(xs2, 128, xb, 256, iv2, Wu[1], di2, q.y, q.z, 1024, 128);
        prop_f32(A2, 1024, bu[1], 128, true, xb, di2, sf2, q);
    }
    // ---- up 2 (tc) ----
    k_xwu_cat<<<2048 / 4, 256>>>(xs1, 64, xb, 128, iv1, Wu[2], di1, q.y, q.zc, 2048, 64);
    prop_tc(A1b, 2048, bu[2], 64, true, xb, di1, sf1, q);

    // ---- up 3 (sparse), NO relu ----
    {
        dim3 bx(32, 8);
        k_xwu<<<dim3(1, 512), bx>>>(xs0, 32, xb, 64, iv0, Wu[3], di0, q.y, q.z, 4096, 32);
        k_sprop<<<4096, 64>>>(offD, inl, selfn, q.z, q.y, di0, sf0, bu[3], xb, 32, 0, 0);
    }

    // ---- final GCN (sparse) + fused softmax -> d_out ----
    {
        dim3 bx(32, 8);
        k_xw<<<dim3(2, 512), bx>>>(xb, Wo, di0, q.y, q.z, 4096, 32, 37);
        k_sprop<<<4096, 64>>>(offD, inl, selfn, q.z, q.y, di0, sf0, bo, (float*)d_out, 37, 0, 1);
    }
}